// round 1
// baseline (speedup 1.0000x reference)
#include <cuda_runtime.h>
#include <math.h>
#include <stdint.h>

// Problem constants
#define NBAT   16384            // B
#define NMAST  8                // agents per group
#define NB     (NBAT * NMAST)   // 131072 rows
#define IN_DIM 128
#define H_DIM  256
#define A_DIM  64
#define NA_DIM 32
#define KCAT   (IN_DIM + A_DIM + H_DIM)   // 448
#define NGATE  (4 * H_DIM)                // 1024

// ---------------- scratch (device globals; no allocation allowed) ----------
__device__ float g_x[(size_t)NB * H_DIM];        // encoded x            134MB
__device__ float g_q[(size_t)NB * A_DIM];        //                       34MB
__device__ float g_k[(size_t)NB * A_DIM];
__device__ float g_v[(size_t)NB * A_DIM];
__device__ float g_e[(size_t)NB * A_DIM];
__device__ float g_fin[(size_t)NB * KCAT];       // [mo | e | hidden]    235MB
__device__ float g_wcat[(size_t)NGATE * KCAT];   // [W_ih | W_hh]        1.8MB
__device__ float g_bcat[NGATE];
__device__ float g_gates[(size_t)NB * NGATE];    //                      537MB

// ---------------- generic SGEMM: C[M,N] = act(A[M,K] * B[N,K]^T + bias) ----
// BM=BN=128, BK=8, 256 threads, 8x8 per-thread tile.
// M must be a multiple of 128 (true for all calls). N may be < BN (guarded).
#define BM 128
#define BN 128
#define BK 8

__global__ __launch_bounds__(256) void sgemm_kernel(
    const float* __restrict__ A, const float* __restrict__ Bw,
    const float* __restrict__ bias, float* __restrict__ C,
    int M, int N, int K, int act)
{
    __shared__ float As[BK][BM];
    __shared__ float Bs[BK][BN];

    const int tid = threadIdx.x;
    const int bm  = blockIdx.y * BM;
    const int bn  = blockIdx.x * BN;
    const int tx  = tid & 15;        // 0..15 -> 8 cols each
    const int ty  = tid >> 4;        // 0..15 -> 8 rows each
    const int lm  = tid >> 1;        // 0..127 (row within tile for loads)
    const int lk  = (tid & 1) << 2;  // 0 or 4

    float acc[8][8] = {};

    const float* Ap = A + (size_t)(bm + lm) * K + lk;
    const bool   bvalid = (bn + lm) < N;
    const float* Bp = Bw + (size_t)(bvalid ? (bn + lm) : 0) * K + lk;

    for (int k0 = 0; k0 < K; k0 += BK) {
        float4 av = *(const float4*)(Ap + k0);
        float4 bv = make_float4(0.f, 0.f, 0.f, 0.f);
        if (bvalid) bv = *(const float4*)(Bp + k0);

        __syncthreads();
        As[lk + 0][lm] = av.x; As[lk + 1][lm] = av.y;
        As[lk + 2][lm] = av.z; As[lk + 3][lm] = av.w;
        Bs[lk + 0][lm] = bv.x; Bs[lk + 1][lm] = bv.y;
        Bs[lk + 2][lm] = bv.z; Bs[lk + 3][lm] = bv.w;
        __syncthreads();

        #pragma unroll
        for (int kk = 0; kk < BK; kk++) {
            float a[8], b[8];
            #pragma unroll
            for (int i = 0; i < 8; i++) a[i] = As[kk][ty * 8 + i];
            #pragma unroll
            for (int j = 0; j < 8; j++) b[j] = Bs[kk][tx * 8 + j];
            #pragma unroll
            for (int i = 0; i < 8; i++)
                #pragma unroll
                for (int j = 0; j < 8; j++)
                    acc[i][j] = fmaf(a[i], b[j], acc[i][j]);
        }
    }

    #pragma unroll
    for (int i = 0; i < 8; i++) {
        int m = bm + ty * 8 + i;
        float* Cr = C + (size_t)m * N;
        #pragma unroll
        for (int j = 0; j < 8; j++) {
            int n = bn + tx * 8 + j;
            if (n < N) {
                float v = acc[i][j];
                if (bias) v += bias[n];
                if (act)  v = fmaxf(v, 0.f);
                Cr[n] = v;
            }
        }
    }
}

// ---------------- attention: one warp per group of 8 agents ----------------
// scores = q k^T / 8, diag masked to -1e9, softmax over j, e = w v
__global__ __launch_bounds__(128) void attn_kernel(
    const float* __restrict__ Q, const float* __restrict__ Kk,
    const float* __restrict__ V, float* __restrict__ E)
{
    __shared__ float sq[4][8][68];
    __shared__ float sk[4][8][68];
    __shared__ float sv[4][8][68];

    const int warp = threadIdx.x >> 5;
    const int lane = threadIdx.x & 31;
    const int g    = blockIdx.x * 4 + warp;
    const size_t base = (size_t)g * 8 * A_DIM;

    // cooperative load of q,k,v tiles (8x64 each) for this group
    for (int idx = lane; idx < 128; idx += 32) {
        int i  = idx >> 4;
        int a4 = (idx & 15) * 4;
        float4 t;
        t = *(const float4*)(Q + base + i * A_DIM + a4);
        sq[warp][i][a4+0]=t.x; sq[warp][i][a4+1]=t.y; sq[warp][i][a4+2]=t.z; sq[warp][i][a4+3]=t.w;
        t = *(const float4*)(Kk + base + i * A_DIM + a4);
        sk[warp][i][a4+0]=t.x; sk[warp][i][a4+1]=t.y; sk[warp][i][a4+2]=t.z; sk[warp][i][a4+3]=t.w;
        t = *(const float4*)(V + base + i * A_DIM + a4);
        sv[warp][i][a4+0]=t.x; sv[warp][i][a4+1]=t.y; sv[warp][i][a4+2]=t.z; sv[warp][i][a4+3]=t.w;
    }
    __syncwarp();

    // lane l handles scores (i0, j) and (i0+4, j); i0 = l/8, j = l%8
    const int j  = lane & 7;
    const int i0 = lane >> 3;
    const int i1 = i0 + 4;

    float s0 = 0.f, s1 = 0.f;
    #pragma unroll
    for (int a = 0; a < A_DIM; a++) {
        float kv = sk[warp][j][a];
        s0 = fmaf(sq[warp][i0][a], kv, s0);
        s1 = fmaf(sq[warp][i1][a], kv, s1);
    }
    s0 *= 0.125f; s1 *= 0.125f;
    if (i0 == j) s0 = -1e9f;
    if (i1 == j) s1 = -1e9f;

    // softmax over the 8-lane group (lanes i*8 .. i*8+7 share i)
    const unsigned fm = 0xffffffffu;
    float m0 = s0, m1 = s1;
    #pragma unroll
    for (int o = 4; o >= 1; o >>= 1) {
        m0 = fmaxf(m0, __shfl_xor_sync(fm, m0, o));
        m1 = fmaxf(m1, __shfl_xor_sync(fm, m1, o));
    }
    float e0 = expf(s0 - m0), e1 = expf(s1 - m1);
    float z0 = e0, z1 = e1;
    #pragma unroll
    for (int o = 4; o >= 1; o >>= 1) {
        z0 += __shfl_xor_sync(fm, z0, o);
        z1 += __shfl_xor_sync(fm, z1, o);
    }
    float w0 = e0 / z0, w1 = e1 / z1;

    // e[i][a] = sum_j w(i,j) * v[j][a]; lane covers a = lane and lane+32
    float acc[8][2] = {};
    #pragma unroll
    for (int i = 0; i < 8; i++) {
        #pragma unroll
        for (int jj = 0; jj < 8; jj++) {
            float wij = __shfl_sync(fm, (i < 4) ? w0 : w1, ((i & 3) << 3) + jj);
            acc[i][0] = fmaf(wij, sv[warp][jj][lane],      acc[i][0]);
            acc[i][1] = fmaf(wij, sv[warp][jj][lane + 32], acc[i][1]);
        }
    }
    #pragma unroll
    for (int i = 0; i < 8; i++) {
        float* er = E + base + (size_t)i * A_DIM;
        er[lane]      = acc[i][0];
        er[lane + 32] = acc[i][1];
    }
}

// ---------------- pack fin = [master_out | e | hidden] ---------------------
__global__ void pack_fin_kernel(const float* __restrict__ mo,
                                const float* __restrict__ e,
                                const float* __restrict__ hid,
                                float* __restrict__ fin)
{
    int idx = blockIdx.x * blockDim.x + threadIdx.x;   // NB*448
    int r = idx / KCAT;
    int c = idx - r * KCAT;
    float v;
    if (c < IN_DIM)               v = mo[(size_t)r * IN_DIM + c];
    else if (c < IN_DIM + A_DIM)  v = e[(size_t)r * A_DIM + (c - IN_DIM)];
    else                          v = hid[(size_t)r * H_DIM + (c - IN_DIM - A_DIM)];
    fin[idx] = v;
}

// ---------------- pack wcat = [W_ih | W_hh], bcat = b_ih + b_hh ------------
__global__ void pack_w_kernel(const float* __restrict__ wih,
                              const float* __restrict__ whh,
                              const float* __restrict__ bih,
                              const float* __restrict__ bhh,
                              float* __restrict__ wcat,
                              float* __restrict__ bcat)
{
    int idx = blockIdx.x * blockDim.x + threadIdx.x;   // NGATE*448
    if (idx < NGATE * KCAT) {
        int n = idx / KCAT;
        int c = idx - n * KCAT;
        float v;
        if (c < IN_DIM + A_DIM) v = wih[(size_t)n * (IN_DIM + A_DIM) + c];
        else                    v = whh[(size_t)n * H_DIM + (c - IN_DIM - A_DIM)];
        wcat[idx] = v;
    }
    if (idx < NGATE) bcat[idx] = bih[idx] + bhh[idx];
}

// ---------------- LSTM cell elementwise ------------------------------------
__device__ __forceinline__ float sigmoidf_(float x) { return 1.f / (1.f + expf(-x)); }

__global__ void lstm_kernel(const float* __restrict__ gates,
                            const float* __restrict__ cell,
                            float* __restrict__ hout,
                            float* __restrict__ cout)
{
    int idx = blockIdx.x * blockDim.x + threadIdx.x;   // NB*256
    int r = idx >> 8;
    int h = idx & 255;
    const float* gr = gates + (size_t)r * NGATE;
    float gi = gr[h];
    float gf = gr[H_DIM + h];
    float gg = gr[2 * H_DIM + h];
    float go = gr[3 * H_DIM + h];
    float cp = cell[idx];
    float cn = sigmoidf_(gf) * cp + sigmoidf_(gi) * tanhf(gg);
    float hn = sigmoidf_(go) * tanhf(cn);
    hout[idx] = hn;
    cout[idx] = cn;
}

// ---------------- launch ----------------------------------------------------
extern "C" void kernel_launch(void* const* d_in, const int* in_sizes, int n_in,
                              void* d_out, int out_size)
{
    const float* mo    = (const float*)d_in[0];
    const float* hid   = (const float*)d_in[1];
    const float* cell  = (const float*)d_in[2];
    const float* Wenc  = (const float*)d_in[3];
    const float* benc  = (const float*)d_in[4];
    const float* Wq    = (const float*)d_in[5];
    const float* Wk    = (const float*)d_in[6];
    const float* Wv    = (const float*)d_in[7];
    const float* bv    = (const float*)d_in[8];
    const float* Wih   = (const float*)d_in[9];
    const float* Whh   = (const float*)d_in[10];
    const float* bih   = (const float*)d_in[11];
    const float* bhh   = (const float*)d_in[12];
    const float* Wdec  = (const float*)d_in[13];
    const float* bdec  = (const float*)d_in[14];

    float* out   = (float*)d_out;
    float* m_act = out;                                        // [B,8,32]
    float* h_out = out + (size_t)NB * NA_DIM;                  // [B,8,256]
    float* c_out = h_out + (size_t)NB * H_DIM;                 // [B,8,256]

    float *x, *q, *k, *v, *e, *fin, *wcat, *bcat, *gates;
    cudaGetSymbolAddress((void**)&x,     g_x);
    cudaGetSymbolAddress((void**)&q,     g_q);
    cudaGetSymbolAddress((void**)&k,     g_k);
    cudaGetSymbolAddress((void**)&v,     g_v);
    cudaGetSymbolAddress((void**)&e,     g_e);
    cudaGetSymbolAddress((void**)&fin,   g_fin);
    cudaGetSymbolAddress((void**)&wcat,  g_wcat);
    cudaGetSymbolAddress((void**)&bcat,  g_bcat);
    cudaGetSymbolAddress((void**)&gates, g_gates);

    const int MB = NB / BM;   // 1024

    // 1) x = relu(mo @ Wenc^T + benc)        [NB,256]
    sgemm_kernel<<<dim3(H_DIM / BN, MB), 256>>>(mo, Wenc, benc, x, NB, H_DIM, IN_DIM, 1);

    // 2) q,k,v projections                   [NB,64]
    sgemm_kernel<<<dim3(1, MB), 256>>>(x, Wq, nullptr, q, NB, A_DIM, H_DIM, 0);
    sgemm_kernel<<<dim3(1, MB), 256>>>(x, Wk, nullptr, k, NB, A_DIM, H_DIM, 0);
    sgemm_kernel<<<dim3(1, MB), 256>>>(x, Wv, bv,      v, NB, A_DIM, H_DIM, 1);

    // 3) masked self-attention per group -> e [NB,64]
    attn_kernel<<<NBAT / 4, 128>>>(q, k, v, e);

    // 4) pack concatenated input and weights
    pack_fin_kernel<<<(NB * KCAT) / 256, 256>>>(mo, e, hid, fin);
    pack_w_kernel<<<(NGATE * KCAT + 255) / 256, 256>>>(Wih, Whh, bih, bhh, wcat, bcat);

    // 5) gates = fin @ wcat^T + bcat         [NB,1024]
    sgemm_kernel<<<dim3(NGATE / BN, MB), 256>>>(fin, wcat, bcat, gates, NB, NGATE, KCAT, 0);

    // 6) LSTM elementwise -> h_out, c_out (directly into d_out)
    lstm_kernel<<<(NB * H_DIM) / 256, 256>>>(gates, cell, h_out, c_out);

    // 7) m_actions = h_out @ Wdec^T + bdec   [NB,32]
    sgemm_kernel<<<dim3(1, MB), 256>>>(h_out, Wdec, bdec, m_act, NB, NA_DIM, H_DIM, 0);
}

// round 2
// speedup vs baseline: 2.6909x; 2.6909x over previous
#include <cuda_runtime.h>
#include <math.h>
#include <stdint.h>

// Problem constants
#define NBAT   16384
#define NMAST  8
#define NB     (NBAT * NMAST)   // 131072
#define IN_DIM 128
#define H_DIM  256
#define A_DIM  64
#define NA_DIM 32

// ---------------- scratch ---------------------------------------------------
__device__ float g_x[(size_t)NB * H_DIM];
__device__ float g_q[(size_t)NB * A_DIM];
__device__ float g_k[(size_t)NB * A_DIM];
__device__ float g_v[(size_t)NB * A_DIM];
__device__ float g_e[(size_t)NB * A_DIM];

// ---------------- helpers ----------------------------------------------------
__device__ __forceinline__ uint32_t f2tf(float f) {
    uint32_t u;
    asm("cvt.rna.tf32.f32 %0, %1;" : "=r"(u) : "f"(f));
    return u;
}
__device__ __forceinline__ void mma8(float* c, const uint32_t* a, const uint32_t* b) {
    asm volatile(
        "mma.sync.aligned.m16n8k8.row.col.f32.tf32.tf32.f32 "
        "{%0,%1,%2,%3},{%4,%5,%6,%7},{%8,%9},{%0,%1,%2,%3};\n"
        : "+f"(c[0]), "+f"(c[1]), "+f"(c[2]), "+f"(c[3])
        : "r"(a[0]), "r"(a[1]), "r"(a[2]), "r"(a[3]), "r"(b[0]), "r"(b[1]));
}
__device__ __forceinline__ float sigf(float x) { return 1.f / (1.f + expf(-x)); }

struct GP {
    const float *A, *A1, *A2;
    const float *B0, *B1, *B2;
    const float *bias0, *bias1;
    const float *cell;
    float *out0, *out1, *out2;
};

// MODE 0: encoder  x = relu(mo @ Wenc^T + b)      M=NB N=256 K=128
// MODE 1: qkv      {q,k,v} = x @ W^T (+b,relu v)  M=NB N=64  K=256 (bx picks W)
// MODE 2: gates    fused [mo|e|hid] @ [Wih|Whh]^T + LSTM cell -> h_out,c_out
// MODE 3: decoder  m_act = h_out @ Wdec^T + b     M=NB N=32  K=256
template<int MODE>
__global__ void __launch_bounds__(256, 2) gemm_tf32(GP p) {
    constexpr int BN = (MODE == 1) ? 64 : (MODE == 3) ? 32 : 128;
    constexpr int WC = (MODE == 1) ? 2  : (MODE == 3) ? 1  : 4;
    constexpr int WR = 8 / WC;
    constexpr int MT = 8 / WR;           // m16 tiles per warp
    constexpr int NT = 4;                // n8 tiles per warp
    constexpr int K  = (MODE == 0) ? 128 : (MODE == 2) ? 448 : 256;
    constexpr int ITERS = K / 16;
    constexpr int WTM = MT * 16;

    __shared__ uint32_t As[2][128 * 20];
    __shared__ uint32_t Bs[2][BN * 20];

    const int tid  = threadIdx.x;
    const int lane = tid & 31, warp = tid >> 5;
    const int wr = warp / WC, wc = warp % WC;
    const int q  = lane & 3,  rr = lane >> 2;
    const int m0 = blockIdx.y * 128;
    const int bx = blockIdx.x;

    const int arow = tid >> 2;          // 0..63
    const int akc  = (tid & 3) * 4;     // 0,4,8,12

    auto ldA = [&](int m, int k) -> float4 {
        if constexpr (MODE == 0)
            return *(const float4*)(p.A + (size_t)m * 128 + k);
        else if constexpr (MODE == 1 || MODE == 3)
            return *(const float4*)(p.A + (size_t)m * 256 + k);
        else {
            if (k < 128)      return *(const float4*)(p.A  + (size_t)m * 128 + k);
            else if (k < 192) return *(const float4*)(p.A1 + (size_t)m * 64  + (k - 128));
            else              return *(const float4*)(p.A2 + (size_t)m * 256 + (k - 192));
        }
    };
    auto ldB = [&](int n, int k) -> float4 {
        if constexpr (MODE == 0)
            return *(const float4*)(p.B0 + (size_t)(bx * 128 + n) * 128 + k);
        else if constexpr (MODE == 1) {
            const float* W = (bx == 0) ? p.B0 : (bx == 1) ? p.B1 : p.B2;
            return *(const float4*)(W + (size_t)n * 256 + k);
        } else if constexpr (MODE == 2) {
            int g = n & 3, hl = n >> 2;
            int r = g * 256 + bx * 32 + hl;
            if (k < 192) return *(const float4*)(p.B0 + (size_t)r * 192 + k);
            else         return *(const float4*)(p.B1 + (size_t)r * 256 + (k - 192));
        } else
            return *(const float4*)(p.B0 + (size_t)n * 256 + k);
    };

    float acc[MT][NT][4];
    #pragma unroll
    for (int i = 0; i < MT; i++)
        #pragma unroll
        for (int j = 0; j < NT; j++)
            #pragma unroll
            for (int t = 0; t < 4; t++) acc[i][j][t] = 0.f;

    float4 ra0, ra1, rb0, rb1;
    auto ldg = [&](int k0) {
        ra0 = ldA(m0 + arow, k0 + akc);
        ra1 = ldA(m0 + arow + 64, k0 + akc);
        if constexpr (BN == 128) { rb0 = ldB(arow, k0 + akc); rb1 = ldB(arow + 64, k0 + akc); }
        else if constexpr (BN == 64) { rb0 = ldB(arow, k0 + akc); }
        else { if (tid < 128) rb0 = ldB(arow, k0 + akc); }
    };
    auto sts4 = [&](uint32_t* s, float4 v) {
        s[0] = f2tf(v.x); s[1] = f2tf(v.y); s[2] = f2tf(v.z); s[3] = f2tf(v.w);
    };
    auto stsTile = [&](int buf) {
        sts4(&As[buf][arow * 20 + akc], ra0);
        sts4(&As[buf][(arow + 64) * 20 + akc], ra1);
        if constexpr (BN == 128) {
            sts4(&Bs[buf][arow * 20 + akc], rb0);
            sts4(&Bs[buf][(arow + 64) * 20 + akc], rb1);
        } else if constexpr (BN == 64) {
            sts4(&Bs[buf][arow * 20 + akc], rb0);
        } else {
            if (tid < 128) sts4(&Bs[buf][arow * 20 + akc], rb0);
        }
    };

    ldg(0);
    stsTile(0);

    for (int it = 0; it < ITERS; ++it) {
        __syncthreads();
        if (it + 1 < ITERS) ldg((it + 1) * 16);
        const int cb = it & 1;
        #pragma unroll
        for (int ph = 0; ph < 2; ++ph) {
            uint32_t af[MT][4], bf[NT][2];
            #pragma unroll
            for (int mi = 0; mi < MT; ++mi) {
                const uint32_t* s = &As[cb][(wr * WTM + mi * 16 + rr) * 20 + ph * 8 + q];
                af[mi][0] = s[0]; af[mi][1] = s[160]; af[mi][2] = s[4]; af[mi][3] = s[164];
            }
            #pragma unroll
            for (int ni = 0; ni < NT; ++ni) {
                const uint32_t* s = &Bs[cb][(wc * 32 + ni * 8 + rr) * 20 + ph * 8 + q];
                bf[ni][0] = s[0]; bf[ni][1] = s[4];
            }
            #pragma unroll
            for (int mi = 0; mi < MT; ++mi)
                #pragma unroll
                for (int ni = 0; ni < NT; ++ni)
                    mma8(acc[mi][ni], af[mi], bf[ni]);
        }
        __syncthreads();
        if (it + 1 < ITERS) stsTile((it + 1) & 1);
    }

    // ---------------- epilogues ----------------
    if constexpr (MODE == 0) {
        #pragma unroll
        for (int mi = 0; mi < MT; ++mi)
            #pragma unroll
            for (int ni = 0; ni < NT; ++ni) {
                int n = bx * 128 + wc * 32 + ni * 8 + q * 2;
                int m = m0 + wr * WTM + mi * 16 + rr;
                float b0v = p.bias0[n], b1v = p.bias0[n + 1];
                float2 v0 = make_float2(fmaxf(acc[mi][ni][0] + b0v, 0.f),
                                        fmaxf(acc[mi][ni][1] + b1v, 0.f));
                float2 v1 = make_float2(fmaxf(acc[mi][ni][2] + b0v, 0.f),
                                        fmaxf(acc[mi][ni][3] + b1v, 0.f));
                *(float2*)(p.out0 + (size_t)m * 256 + n) = v0;
                *(float2*)(p.out0 + (size_t)(m + 8) * 256 + n) = v1;
            }
    } else if constexpr (MODE == 1) {
        float* o = (bx == 0) ? p.out0 : (bx == 1) ? p.out1 : p.out2;
        bool act = (bx == 2);
        #pragma unroll
        for (int mi = 0; mi < MT; ++mi)
            #pragma unroll
            for (int ni = 0; ni < NT; ++ni) {
                int n = wc * 32 + ni * 8 + q * 2;
                int m = m0 + wr * WTM + mi * 16 + rr;
                float b0v = act ? p.bias0[n] : 0.f, b1v = act ? p.bias0[n + 1] : 0.f;
                float v0 = acc[mi][ni][0] + b0v, v1 = acc[mi][ni][1] + b1v;
                float v2 = acc[mi][ni][2] + b0v, v3 = acc[mi][ni][3] + b1v;
                if (act) { v0 = fmaxf(v0, 0.f); v1 = fmaxf(v1, 0.f); v2 = fmaxf(v2, 0.f); v3 = fmaxf(v3, 0.f); }
                *(float2*)(o + (size_t)m * 64 + n) = make_float2(v0, v1);
                *(float2*)(o + (size_t)(m + 8) * 64 + n) = make_float2(v2, v3);
            }
    } else if constexpr (MODE == 3) {
        #pragma unroll
        for (int mi = 0; mi < MT; ++mi)
            #pragma unroll
            for (int ni = 0; ni < NT; ++ni) {
                int n = ni * 8 + q * 2;
                int m = m0 + wr * WTM + mi * 16 + rr;
                float b0v = p.bias0[n], b1v = p.bias0[n + 1];
                *(float2*)(p.out0 + (size_t)m * 32 + n) =
                    make_float2(acc[mi][ni][0] + b0v, acc[mi][ni][1] + b1v);
                *(float2*)(p.out0 + (size_t)(m + 8) * 32 + n) =
                    make_float2(acc[mi][ni][2] + b0v, acc[mi][ni][3] + b1v);
            }
    } else {
        // MODE 2: fused LSTM epilogue. Columns n = h_local*4 + gate (gate: i,f,g,o)
        float* smc = (float*)&Bs[0][0];   // cell tile [128][33]
        float* smr = (float*)&As[0][0];   // h tile   [128][33]
        const int h0 = bx * 32;
        for (int i = tid; i < 4096; i += 256) {
            int m = i >> 5, h = i & 31;
            smc[m * 33 + h] = p.cell[(size_t)(m0 + m) * 256 + h0 + h];
        }
        __syncthreads();

        const bool even = (q & 1) == 0;
        #pragma unroll
        for (int ni = 0; ni < NT; ++ni) {
            int nb = wc * 32 + ni * 8;
            int h_loc = (nb >> 2) + (q >> 1);
            int hg = h0 + h_loc;
            int g0 = (q & 1) * 2;
            float bb0 = p.bias0[g0 * 256 + hg] + p.bias1[g0 * 256 + hg];
            float bb1 = p.bias0[(g0 + 1) * 256 + hg] + p.bias1[(g0 + 1) * 256 + hg];
            #pragma unroll
            for (int mi = 0; mi < MT; ++mi) {
                float c0 = acc[mi][ni][0] + bb0, c1 = acc[mi][ni][1] + bb1;
                float c2 = acc[mi][ni][2] + bb0, c3 = acc[mi][ni][3] + bb1;
                float p0 = __shfl_xor_sync(~0u, c0, 1);
                float p1 = __shfl_xor_sync(~0u, c1, 1);
                float p2 = __shfl_xor_sync(~0u, c2, 1);
                float p3 = __shfl_xor_sync(~0u, c3, 1);
                if (even) {
                    // even lane owns gates i (c0/c2), f (c1/c3); partner has g (p0/p2), o (p1/p3)
                    int ml = wr * 64 + mi * 16 + rr;
                    float cp0 = smc[ml * 33 + h_loc];
                    float cp1 = smc[(ml + 8) * 33 + h_loc];
                    float cn0 = sigf(c1) * cp0 + sigf(c0) * tanhf(p0);
                    float hn0 = sigf(p1) * tanhf(cn0);
                    float cn1 = sigf(c3) * cp1 + sigf(c2) * tanhf(p2);
                    float hn1 = sigf(p3) * tanhf(cn1);
                    acc[mi][ni][0] = hn0; acc[mi][ni][1] = cn0;
                    acc[mi][ni][2] = hn1; acc[mi][ni][3] = cn1;
                }
            }
        }
        __syncthreads();   // all cell reads done
        #pragma unroll
        for (int ni = 0; ni < NT; ++ni) {
            int nb = wc * 32 + ni * 8;
            int h_loc = (nb >> 2) + (q >> 1);
            #pragma unroll
            for (int mi = 0; mi < MT; ++mi) {
                if (even) {
                    int ml = wr * 64 + mi * 16 + rr;
                    smr[ml * 33 + h_loc]       = acc[mi][ni][0];
                    smc[ml * 33 + h_loc]       = acc[mi][ni][1];
                    smr[(ml + 8) * 33 + h_loc] = acc[mi][ni][2];
                    smc[(ml + 8) * 33 + h_loc] = acc[mi][ni][3];
                }
            }
        }
        __syncthreads();
        for (int i = tid; i < 4096; i += 256) {
            int m = i >> 5, h = i & 31;
            size_t off = (size_t)(m0 + m) * 256 + h0 + h;
            p.out0[off] = smr[m * 33 + h];
            p.out1[off] = smc[m * 33 + h];
        }
    }
}

// ---------------- attention (unchanged from R1) ----------------------------
__global__ __launch_bounds__(128) void attn_kernel(
    const float* __restrict__ Q, const float* __restrict__ Kk,
    const float* __restrict__ V, float* __restrict__ E)
{
    __shared__ float sq[4][8][68];
    __shared__ float sk[4][8][68];
    __shared__ float sv[4][8][68];

    const int warp = threadIdx.x >> 5;
    const int lane = threadIdx.x & 31;
    const int g    = blockIdx.x * 4 + warp;
    const size_t base = (size_t)g * 8 * A_DIM;

    for (int idx = lane; idx < 128; idx += 32) {
        int i  = idx >> 4;
        int a4 = (idx & 15) * 4;
        float4 t;
        t = *(const float4*)(Q + base + i * A_DIM + a4);
        sq[warp][i][a4+0]=t.x; sq[warp][i][a4+1]=t.y; sq[warp][i][a4+2]=t.z; sq[warp][i][a4+3]=t.w;
        t = *(const float4*)(Kk + base + i * A_DIM + a4);
        sk[warp][i][a4+0]=t.x; sk[warp][i][a4+1]=t.y; sk[warp][i][a4+2]=t.z; sk[warp][i][a4+3]=t.w;
        t = *(const float4*)(V + base + i * A_DIM + a4);
        sv[warp][i][a4+0]=t.x; sv[warp][i][a4+1]=t.y; sv[warp][i][a4+2]=t.z; sv[warp][i][a4+3]=t.w;
    }
    __syncwarp();

    const int j  = lane & 7;
    const int i0 = lane >> 3;
    const int i1 = i0 + 4;

    float s0 = 0.f, s1 = 0.f;
    #pragma unroll
    for (int a = 0; a < A_DIM; a++) {
        float kv = sk[warp][j][a];
        s0 = fmaf(sq[warp][i0][a], kv, s0);
        s1 = fmaf(sq[warp][i1][a], kv, s1);
    }
    s0 *= 0.125f; s1 *= 0.125f;
    if (i0 == j) s0 = -1e9f;
    if (i1 == j) s1 = -1e9f;

    const unsigned fm = 0xffffffffu;
    float m0 = s0, m1 = s1;
    #pragma unroll
    for (int o = 4; o >= 1; o >>= 1) {
        m0 = fmaxf(m0, __shfl_xor_sync(fm, m0, o));
        m1 = fmaxf(m1, __shfl_xor_sync(fm, m1, o));
    }
    float e0 = expf(s0 - m0), e1 = expf(s1 - m1);
    float z0 = e0, z1 = e1;
    #pragma unroll
    for (int o = 4; o >= 1; o >>= 1) {
        z0 += __shfl_xor_sync(fm, z0, o);
        z1 += __shfl_xor_sync(fm, z1, o);
    }
    float w0 = e0 / z0, w1 = e1 / z1;

    float accv[8][2] = {};
    #pragma unroll
    for (int i = 0; i < 8; i++) {
        #pragma unroll
        for (int jj = 0; jj < 8; jj++) {
            float wij = __shfl_sync(fm, (i < 4) ? w0 : w1, ((i & 3) << 3) + jj);
            accv[i][0] = fmaf(wij, sv[warp][jj][lane],      accv[i][0]);
            accv[i][1] = fmaf(wij, sv[warp][jj][lane + 32], accv[i][1]);
        }
    }
    #pragma unroll
    for (int i = 0; i < 8; i++) {
        float* er = E + base + (size_t)i * A_DIM;
        er[lane]      = accv[i][0];
        er[lane + 32] = accv[i][1];
    }
}

// ---------------- launch ----------------------------------------------------
extern "C" void kernel_launch(void* const* d_in, const int* in_sizes, int n_in,
                              void* d_out, int out_size)
{
    const float* mo    = (const float*)d_in[0];
    const float* hid   = (const float*)d_in[1];
    const float* cell  = (const float*)d_in[2];
    const float* Wenc  = (const float*)d_in[3];
    const float* benc  = (const float*)d_in[4];
    const float* Wq    = (const float*)d_in[5];
    const float* Wk    = (const float*)d_in[6];
    const float* Wv    = (const float*)d_in[7];
    const float* bv    = (const float*)d_in[8];
    const float* Wih   = (const float*)d_in[9];
    const float* Whh   = (const float*)d_in[10];
    const float* bih   = (const float*)d_in[11];
    const float* bhh   = (const float*)d_in[12];
    const float* Wdec  = (const float*)d_in[13];
    const float* bdec  = (const float*)d_in[14];

    float* out   = (float*)d_out;
    float* m_act = out;
    float* h_out = out + (size_t)NB * NA_DIM;
    float* c_out = h_out + (size_t)NB * H_DIM;

    float *x, *q, *k, *v, *e;
    cudaGetSymbolAddress((void**)&x, g_x);
    cudaGetSymbolAddress((void**)&q, g_q);
    cudaGetSymbolAddress((void**)&k, g_k);
    cudaGetSymbolAddress((void**)&v, g_v);
    cudaGetSymbolAddress((void**)&e, g_e);

    // 1) encoder
    {
        GP p{}; p.A = mo; p.B0 = Wenc; p.bias0 = benc; p.out0 = x;
        gemm_tf32<0><<<dim3(2, 1024), 256>>>(p);
    }
    // 2) q,k,v
    {
        GP p{}; p.A = x; p.B0 = Wq; p.B1 = Wk; p.B2 = Wv; p.bias0 = bv;
        p.out0 = q; p.out1 = k; p.out2 = v;
        gemm_tf32<1><<<dim3(3, 1024), 256>>>(p);
    }
    // 3) attention
    attn_kernel<<<NBAT / 4, 128>>>(q, k, v, e);
    // 4) gates GEMM + fused LSTM
    {
        GP p{}; p.A = mo; p.A1 = e; p.A2 = hid;
        p.B0 = Wih; p.B1 = Whh; p.bias0 = bih; p.bias1 = bhh;
        p.cell = cell; p.out0 = h_out; p.out1 = c_out;
        gemm_tf32<2><<<dim3(8, 1024), 256>>>(p);
    }
    // 5) decoder
    {
        GP p{}; p.A = h_out; p.B0 = Wdec; p.bias0 = bdec; p.out0 = m_act;
        gemm_tf32<3><<<dim3(1, 1024), 256>>>(p);
    }
}

// round 3
// speedup vs baseline: 2.8781x; 1.0696x over previous
#include <cuda_runtime.h>
#include <math.h>
#include <stdint.h>

// Problem constants
#define NBAT   16384
#define NMAST  8
#define NB     (NBAT * NMAST)   // 131072
#define IN_DIM 128
#define H_DIM  256
#define A_DIM  64
#define NA_DIM 32

// ---------------- scratch ---------------------------------------------------
__device__ float g_x[(size_t)NB * H_DIM];
__device__ float g_q[(size_t)NB * A_DIM];
__device__ float g_k[(size_t)NB * A_DIM];
__device__ float g_v[(size_t)NB * A_DIM];
__device__ float g_e[(size_t)NB * A_DIM];

// ---------------- helpers ----------------------------------------------------
__device__ __forceinline__ uint32_t f2tf(float f) {
    uint32_t u;
    asm("cvt.rna.tf32.f32 %0, %1;" : "=r"(u) : "f"(f));
    return u;
}
__device__ __forceinline__ void mma8(float* c, const uint32_t* a, const uint32_t* b) {
    asm volatile(
        "mma.sync.aligned.m16n8k8.row.col.f32.tf32.tf32.f32 "
        "{%0,%1,%2,%3},{%4,%5,%6,%7},{%8,%9},{%0,%1,%2,%3};\n"
        : "+f"(c[0]), "+f"(c[1]), "+f"(c[2]), "+f"(c[3])
        : "r"(a[0]), "r"(a[1]), "r"(a[2]), "r"(a[3]), "r"(b[0]), "r"(b[1]));
}
// ldmatrix x4 (b16 view of tf32 data): one call = full A fragment of a 16x8
// tf32 tile, or B fragments of two adjacent 8x8 n-tiles.
__device__ __forceinline__ void ldsm4(uint32_t* r, uint32_t saddr) {
    asm volatile("ldmatrix.sync.aligned.m8n8.x4.shared.b16 {%0,%1,%2,%3}, [%4];"
        : "=r"(r[0]), "=r"(r[1]), "=r"(r[2]), "=r"(r[3]) : "r"(saddr));
}
__device__ __forceinline__ float sigf(float x) { return 1.f / (1.f + expf(-x)); }

struct GP {
    const float *A, *A1, *A2;
    const float *B0, *B1, *B2;
    const float *bias0, *bias1;
    const float *cell;
    float *out0, *out1, *out2;
};

// MODE 0: encoder  x = relu(mo @ Wenc^T + b)      M=NB N=256 K=128
// MODE 1: qkv      {q,k,v} = x @ W^T (+b,relu v)  M=NB N=64  K=256 (bx picks W)
// MODE 2: gates    fused [mo|e|hid] @ [Wih|Whh]^T + LSTM cell -> h_out,c_out
// MODE 3: decoder  m_act = h_out @ Wdec^T + b     M=NB N=32  K=256
template<int MODE>
__global__ void __launch_bounds__(256, 2) gemm_tf32(GP p) {
    constexpr int BN = (MODE == 1) ? 64 : (MODE == 3) ? 32 : 128;
    constexpr int WC = (MODE == 1) ? 2  : (MODE == 3) ? 1  : 4;
    constexpr int WR = 8 / WC;
    constexpr int MT = 8 / WR;           // m16 tiles per warp
    constexpr int NT = 4;                // n8 tiles per warp
    constexpr int K  = (MODE == 0) ? 128 : (MODE == 2) ? 448 : 256;
    constexpr int ITERS = K / 16;
    constexpr int WTM = MT * 16;

    __shared__ uint32_t As[2][128 * 20];
    __shared__ uint32_t Bs[2][BN * 20];

    const int tid  = threadIdx.x;
    const int lane = tid & 31, warp = tid >> 5;
    const int wr = warp / WC, wc = warp % WC;
    const int q  = lane & 3,  rr = lane >> 2;
    const int m0 = blockIdx.y * 128;
    const int bx = blockIdx.x;

    const int arow = tid >> 2;          // 0..63
    const int akc  = (tid & 3) * 4;     // 0,4,8,12

    auto ldA = [&](int m, int k) -> float4 {
        if constexpr (MODE == 0)
            return *(const float4*)(p.A + (size_t)m * 128 + k);
        else if constexpr (MODE == 1 || MODE == 3)
            return *(const float4*)(p.A + (size_t)m * 256 + k);
        else {
            if (k < 128)      return *(const float4*)(p.A  + (size_t)m * 128 + k);
            else if (k < 192) return *(const float4*)(p.A1 + (size_t)m * 64  + (k - 128));
            else              return *(const float4*)(p.A2 + (size_t)m * 256 + (k - 192));
        }
    };
    auto ldB = [&](int n, int k) -> float4 {
        if constexpr (MODE == 0)
            return *(const float4*)(p.B0 + (size_t)(bx * 128 + n) * 128 + k);
        else if constexpr (MODE == 1) {
            const float* W = (bx == 0) ? p.B0 : (bx == 1) ? p.B1 : p.B2;
            return *(const float4*)(W + (size_t)n * 256 + k);
        } else if constexpr (MODE == 2) {
            int g = n & 3, hl = n >> 2;
            int r = g * 256 + bx * 32 + hl;
            if (k < 192) return *(const float4*)(p.B0 + (size_t)r * 192 + k);
            else         return *(const float4*)(p.B1 + (size_t)r * 256 + (k - 192));
        } else
            return *(const float4*)(p.B0 + (size_t)n * 256 + k);
    };

    float acc[MT][NT][4];
    #pragma unroll
    for (int i = 0; i < MT; i++)
        #pragma unroll
        for (int j = 0; j < NT; j++)
            #pragma unroll
            for (int t = 0; t < 4; t++) acc[i][j][t] = 0.f;

    float4 ra0, ra1, rb0, rb1;
    auto ldg = [&](int k0) {
        ra0 = ldA(m0 + arow, k0 + akc);
        ra1 = ldA(m0 + arow + 64, k0 + akc);
        if constexpr (BN == 128) { rb0 = ldB(arow, k0 + akc); rb1 = ldB(arow + 64, k0 + akc); }
        else if constexpr (BN == 64) { rb0 = ldB(arow, k0 + akc); }
        else { if (tid < 128) rb0 = ldB(arow, k0 + akc); }
    };
    auto sts4 = [&](uint32_t* s, float4 v) {
        s[0] = f2tf(v.x); s[1] = f2tf(v.y); s[2] = f2tf(v.z); s[3] = f2tf(v.w);
    };
    auto stsTile = [&](int buf) {
        sts4(&As[buf][arow * 20 + akc], ra0);
        sts4(&As[buf][(arow + 64) * 20 + akc], ra1);
        if constexpr (BN == 128) {
            sts4(&Bs[buf][arow * 20 + akc], rb0);
            sts4(&Bs[buf][(arow + 64) * 20 + akc], rb1);
        } else if constexpr (BN == 64) {
            sts4(&Bs[buf][arow * 20 + akc], rb0);
        } else {
            if (tid < 128) sts4(&Bs[buf][arow * 20 + akc], rb0);
        }
    };

    // ldmatrix lane addressing (byte offsets within one buffer)
    const uint32_t As_base = (uint32_t)__cvta_generic_to_shared(&As[0][0]);
    const uint32_t Bs_base = (uint32_t)__cvta_generic_to_shared(&Bs[0][0]);
    constexpr uint32_t ABUF = 128 * 20 * 4;
    constexpr uint32_t BBUF = BN * 20 * 4;
    const int a_r = lane & 15, a_h = lane >> 4;          // A: lanes 0-15 rows, 16-31 k+4 half
    const int b_g = lane >> 3, b_rl = lane & 7;          // B: 4 groups of 8 lanes
    const int b_row = (b_g >> 1) * 8 + b_rl;             // row within 16-row pair tile
    const int b_k4  = (b_g & 1) * 4;                     // k half

    ldg(0);
    stsTile(0);
    __syncthreads();

    for (int it = 0; it < ITERS; ++it) {
        if (it + 1 < ITERS) ldg((it + 1) * 16);
        const int cb = it & 1;
        const uint32_t Ab = As_base + cb * ABUF;
        const uint32_t Bb = Bs_base + cb * BBUF;
        #pragma unroll
        for (int ph = 0; ph < 2; ++ph) {
            uint32_t af[MT][4], bf[NT][2];
            #pragma unroll
            for (int mi = 0; mi < MT; ++mi)
                ldsm4(af[mi], Ab + 4u * ((wr * WTM + mi * 16 + a_r) * 20 + ph * 8 + a_h * 4));
            #pragma unroll
            for (int pi = 0; pi < NT / 2; ++pi)
                ldsm4(&bf[2 * pi][0], Bb + 4u * ((wc * 32 + pi * 16 + b_row) * 20 + ph * 8 + b_k4));
            #pragma unroll
            for (int mi = 0; mi < MT; ++mi)
                #pragma unroll
                for (int ni = 0; ni < NT; ++ni)
                    mma8(acc[mi][ni], af[mi], bf[ni]);
        }
        if (it + 1 < ITERS) stsTile((it + 1) & 1);
        __syncthreads();
    }

    // ---------------- epilogues ----------------
    if constexpr (MODE == 0) {
        #pragma unroll
        for (int mi = 0; mi < MT; ++mi)
            #pragma unroll
            for (int ni = 0; ni < NT; ++ni) {
                int n = bx * 128 + wc * 32 + ni * 8 + q * 2;
                int m = m0 + wr * WTM + mi * 16 + rr;
                float b0v = p.bias0[n], b1v = p.bias0[n + 1];
                float2 v0 = make_float2(fmaxf(acc[mi][ni][0] + b0v, 0.f),
                                        fmaxf(acc[mi][ni][1] + b1v, 0.f));
                float2 v1 = make_float2(fmaxf(acc[mi][ni][2] + b0v, 0.f),
                                        fmaxf(acc[mi][ni][3] + b1v, 0.f));
                *(float2*)(p.out0 + (size_t)m * 256 + n) = v0;
                *(float2*)(p.out0 + (size_t)(m + 8) * 256 + n) = v1;
            }
    } else if constexpr (MODE == 1) {
        float* o = (bx == 0) ? p.out0 : (bx == 1) ? p.out1 : p.out2;
        bool act = (bx == 2);
        #pragma unroll
        for (int mi = 0; mi < MT; ++mi)
            #pragma unroll
            for (int ni = 0; ni < NT; ++ni) {
                int n = wc * 32 + ni * 8 + q * 2;
                int m = m0 + wr * WTM + mi * 16 + rr;
                float b0v = act ? p.bias0[n] : 0.f, b1v = act ? p.bias0[n + 1] : 0.f;
                float v0 = acc[mi][ni][0] + b0v, v1 = acc[mi][ni][1] + b1v;
                float v2 = acc[mi][ni][2] + b0v, v3 = acc[mi][ni][3] + b1v;
                if (act) { v0 = fmaxf(v0, 0.f); v1 = fmaxf(v1, 0.f); v2 = fmaxf(v2, 0.f); v3 = fmaxf(v3, 0.f); }
                *(float2*)(o + (size_t)m * 64 + n) = make_float2(v0, v1);
                *(float2*)(o + (size_t)(m + 8) * 64 + n) = make_float2(v2, v3);
            }
    } else if constexpr (MODE == 3) {
        #pragma unroll
        for (int mi = 0; mi < MT; ++mi)
            #pragma unroll
            for (int ni = 0; ni < NT; ++ni) {
                int n = ni * 8 + q * 2;
                int m = m0 + wr * WTM + mi * 16 + rr;
                float b0v = p.bias0[n], b1v = p.bias0[n + 1];
                *(float2*)(p.out0 + (size_t)m * 32 + n) =
                    make_float2(acc[mi][ni][0] + b0v, acc[mi][ni][1] + b1v);
                *(float2*)(p.out0 + (size_t)(m + 8) * 32 + n) =
                    make_float2(acc[mi][ni][2] + b0v, acc[mi][ni][3] + b1v);
            }
    } else {
        // MODE 2: fused LSTM epilogue. Columns n = h_local*4 + gate (gate: i,f,g,o)
        float* smc = (float*)&Bs[0][0];   // cell tile [128][33]
        float* smr = (float*)&As[0][0];   // h tile   [128][33]
        const int h0 = bx * 32;
        for (int i = tid; i < 4096; i += 256) {
            int m = i >> 5, h = i & 31;
            smc[m * 33 + h] = p.cell[(size_t)(m0 + m) * 256 + h0 + h];
        }
        __syncthreads();

        const bool even = (q & 1) == 0;
        #pragma unroll
        for (int ni = 0; ni < NT; ++ni) {
            int nb = wc * 32 + ni * 8;
            int h_loc = (nb >> 2) + (q >> 1);
            int hg = h0 + h_loc;
            int g0 = (q & 1) * 2;
            float bb0 = p.bias0[g0 * 256 + hg] + p.bias1[g0 * 256 + hg];
            float bb1 = p.bias0[(g0 + 1) * 256 + hg] + p.bias1[(g0 + 1) * 256 + hg];
            #pragma unroll
            for (int mi = 0; mi < MT; ++mi) {
                float c0 = acc[mi][ni][0] + bb0, c1 = acc[mi][ni][1] + bb1;
                float c2 = acc[mi][ni][2] + bb0, c3 = acc[mi][ni][3] + bb1;
                float p0 = __shfl_xor_sync(~0u, c0, 1);
                float p1 = __shfl_xor_sync(~0u, c1, 1);
                float p2 = __shfl_xor_sync(~0u, c2, 1);
                float p3 = __shfl_xor_sync(~0u, c3, 1);
                if (even) {
                    // even lane owns gates i (c0/c2), f (c1/c3); partner has g (p0/p2), o (p1/p3)
                    int ml = wr * 64 + mi * 16 + rr;
                    float cp0 = smc[ml * 33 + h_loc];
                    float cp1 = smc[(ml + 8) * 33 + h_loc];
                    float cn0 = sigf(c1) * cp0 + sigf(c0) * tanhf(p0);
                    float hn0 = sigf(p1) * tanhf(cn0);
                    float cn1 = sigf(c3) * cp1 + sigf(c2) * tanhf(p2);
                    float hn1 = sigf(p3) * tanhf(cn1);
                    acc[mi][ni][0] = hn0; acc[mi][ni][1] = cn0;
                    acc[mi][ni][2] = hn1; acc[mi][ni][3] = cn1;
                }
            }
        }
        __syncthreads();   // all cell reads done
        #pragma unroll
        for (int ni = 0; ni < NT; ++ni) {
            int nb = wc * 32 + ni * 8;
            int h_loc = (nb >> 2) + (q >> 1);
            #pragma unroll
            for (int mi = 0; mi < MT; ++mi) {
                if (even) {
                    int ml = wr * 64 + mi * 16 + rr;
                    smr[ml * 33 + h_loc]       = acc[mi][ni][0];
                    smc[ml * 33 + h_loc]       = acc[mi][ni][1];
                    smr[(ml + 8) * 33 + h_loc] = acc[mi][ni][2];
                    smc[(ml + 8) * 33 + h_loc] = acc[mi][ni][3];
                }
            }
        }
        __syncthreads();
        for (int i = tid; i < 4096; i += 256) {
            int m = i >> 5, h = i & 31;
            size_t off = (size_t)(m0 + m) * 256 + h0 + h;
            p.out0[off] = smr[m * 33 + h];
            p.out1[off] = smc[m * 33 + h];
        }
    }
}

// ---------------- attention (unchanged) -------------------------------------
__global__ __launch_bounds__(128) void attn_kernel(
    const float* __restrict__ Q, const float* __restrict__ Kk,
    const float* __restrict__ V, float* __restrict__ E)
{
    __shared__ float sq[4][8][68];
    __shared__ float sk[4][8][68];
    __shared__ float sv[4][8][68];

    const int warp = threadIdx.x >> 5;
    const int lane = threadIdx.x & 31;
    const int g    = blockIdx.x * 4 + warp;
    const size_t base = (size_t)g * 8 * A_DIM;

    for (int idx = lane; idx < 128; idx += 32) {
        int i  = idx >> 4;
        int a4 = (idx & 15) * 4;
        float4 t;
        t = *(const float4*)(Q + base + i * A_DIM + a4);
        sq[warp][i][a4+0]=t.x; sq[warp][i][a4+1]=t.y; sq[warp][i][a4+2]=t.z; sq[warp][i][a4+3]=t.w;
        t = *(const float4*)(Kk + base + i * A_DIM + a4);
        sk[warp][i][a4+0]=t.x; sk[warp][i][a4+1]=t.y; sk[warp][i][a4+2]=t.z; sk[warp][i][a4+3]=t.w;
        t = *(const float4*)(V + base + i * A_DIM + a4);
        sv[warp][i][a4+0]=t.x; sv[warp][i][a4+1]=t.y; sv[warp][i][a4+2]=t.z; sv[warp][i][a4+3]=t.w;
    }
    __syncwarp();

    const int j  = lane & 7;
    const int i0 = lane >> 3;
    const int i1 = i0 + 4;

    float s0 = 0.f, s1 = 0.f;
    #pragma unroll
    for (int a = 0; a < A_DIM; a++) {
        float kv = sk[warp][j][a];
        s0 = fmaf(sq[warp][i0][a], kv, s0);
        s1 = fmaf(sq[warp][i1][a], kv, s1);
    }
    s0 *= 0.125f; s1 *= 0.125f;
    if (i0 == j) s0 = -1e9f;
    if (i1 == j) s1 = -1e9f;

    const unsigned fm = 0xffffffffu;
    float m0 = s0, m1 = s1;
    #pragma unroll
    for (int o = 4; o >= 1; o >>= 1) {
        m0 = fmaxf(m0, __shfl_xor_sync(fm, m0, o));
        m1 = fmaxf(m1, __shfl_xor_sync(fm, m1, o));
    }
    float e0 = expf(s0 - m0), e1 = expf(s1 - m1);
    float z0 = e0, z1 = e1;
    #pragma unroll
    for (int o = 4; o >= 1; o >>= 1) {
        z0 += __shfl_xor_sync(fm, z0, o);
        z1 += __shfl_xor_sync(fm, z1, o);
    }
    float w0 = e0 / z0, w1 = e1 / z1;

    float accv[8][2] = {};
    #pragma unroll
    for (int i = 0; i < 8; i++) {
        #pragma unroll
        for (int jj = 0; jj < 8; jj++) {
            float wij = __shfl_sync(fm, (i < 4) ? w0 : w1, ((i & 3) << 3) + jj);
            accv[i][0] = fmaf(wij, sv[warp][jj][lane],      accv[i][0]);
            accv[i][1] = fmaf(wij, sv[warp][jj][lane + 32], accv[i][1]);
        }
    }
    #pragma unroll
    for (int i = 0; i < 8; i++) {
        float* er = E + base + (size_t)i * A_DIM;
        er[lane]      = accv[i][0];
        er[lane + 32] = accv[i][1];
    }
}

// ---------------- launch ----------------------------------------------------
extern "C" void kernel_launch(void* const* d_in, const int* in_sizes, int n_in,
                              void* d_out, int out_size)
{
    const float* mo    = (const float*)d_in[0];
    const float* hid   = (const float*)d_in[1];
    const float* cell  = (const float*)d_in[2];
    const float* Wenc  = (const float*)d_in[3];
    const float* benc  = (const float*)d_in[4];
    const float* Wq    = (const float*)d_in[5];
    const float* Wk    = (const float*)d_in[6];
    const float* Wv    = (const float*)d_in[7];
    const float* bv    = (const float*)d_in[8];
    const float* Wih   = (const float*)d_in[9];
    const float* Whh   = (const float*)d_in[10];
    const float* bih   = (const float*)d_in[11];
    const float* bhh   = (const float*)d_in[12];
    const float* Wdec  = (const float*)d_in[13];
    const float* bdec  = (const float*)d_in[14];

    float* out   = (float*)d_out;
    float* m_act = out;
    float* h_out = out + (size_t)NB * NA_DIM;
    float* c_out = h_out + (size_t)NB * H_DIM;

    float *x, *q, *k, *v, *e;
    cudaGetSymbolAddress((void**)&x, g_x);
    cudaGetSymbolAddress((void**)&q, g_q);
    cudaGetSymbolAddress((void**)&k, g_k);
    cudaGetSymbolAddress((void**)&v, g_v);
    cudaGetSymbolAddress((void**)&e, g_e);

    // 1) encoder
    {
        GP p{}; p.A = mo; p.B0 = Wenc; p.bias0 = benc; p.out0 = x;
        gemm_tf32<0><<<dim3(2, 1024), 256>>>(p);
    }
    // 2) q,k,v
    {
        GP p{}; p.A = x; p.B0 = Wq; p.B1 = Wk; p.B2 = Wv; p.bias0 = bv;
        p.out0 = q; p.out1 = k; p.out2 = v;
        gemm_tf32<1><<<dim3(3, 1024), 256>>>(p);
    }
    // 3) attention
    attn_kernel<<<NBAT / 4, 128>>>(q, k, v, e);
    // 4) gates GEMM + fused LSTM
    {
        GP p{}; p.A = mo; p.A1 = e; p.A2 = hid;
        p.B0 = Wih; p.B1 = Whh; p.bias0 = bih; p.bias1 = bhh;
        p.cell = cell; p.out0 = h_out; p.out1 = c_out;
        gemm_tf32<2><<<dim3(8, 1024), 256>>>(p);
    }
    // 5) decoder
    {
        GP p{}; p.A = h_out; p.B0 = Wdec; p.bias0 = bdec; p.out0 = m_act;
        gemm_tf32<3><<<dim3(1, 1024), 256>>>(p);
    }
}

// round 4
// speedup vs baseline: 3.1767x; 1.1037x over previous
#include <cuda_runtime.h>
#include <math.h>
#include <stdint.h>

// Problem constants
#define NBAT   16384
#define NMAST  8
#define NB     (NBAT * NMAST)   // 131072
#define IN_DIM 128
#define H_DIM  256
#define A_DIM  64
#define NA_DIM 32

// ---------------- scratch (tf32 bit arrays are uint32_t) --------------------
__device__ uint32_t g_moT [(size_t)NB * IN_DIM];
__device__ uint32_t g_hidT[(size_t)NB * H_DIM];
__device__ uint32_t g_x   [(size_t)NB * H_DIM];   // encoder out, tf32 bits
__device__ float    g_q   [(size_t)NB * A_DIM];
__device__ float    g_k   [(size_t)NB * A_DIM];
__device__ float    g_v   [(size_t)NB * A_DIM];
__device__ uint32_t g_eT  [(size_t)NB * A_DIM];   // attention out, tf32 bits
__device__ uint32_t g_hT  [(size_t)NB * H_DIM];   // h_out copy, tf32 bits
__device__ uint32_t g_wencT[256 * 128];
__device__ uint32_t g_wqkvT[3 * 64 * 256];
__device__ uint32_t g_wcatT[1024 * 448];          // gate-interleaved [h*4+g][448]
__device__ uint32_t g_wdecT[32 * 256];

// ---------------- helpers ----------------------------------------------------
__device__ __forceinline__ uint32_t f2tf(float f) {
    uint32_t u;
    asm("cvt.rna.tf32.f32 %0, %1;" : "=r"(u) : "f"(f));
    return u;
}
__device__ __forceinline__ void mma8(float* c, const uint32_t* a, const uint32_t* b) {
    asm volatile(
        "mma.sync.aligned.m16n8k8.row.col.f32.tf32.tf32.f32 "
        "{%0,%1,%2,%3},{%4,%5,%6,%7},{%8,%9},{%0,%1,%2,%3};\n"
        : "+f"(c[0]), "+f"(c[1]), "+f"(c[2]), "+f"(c[3])
        : "r"(a[0]), "r"(a[1]), "r"(a[2]), "r"(a[3]), "r"(b[0]), "r"(b[1]));
}
__device__ __forceinline__ void ldsm4(uint32_t* r, uint32_t saddr) {
    asm volatile("ldmatrix.sync.aligned.m8n8.x4.shared.b16 {%0,%1,%2,%3}, [%4];"
        : "=r"(r[0]), "=r"(r[1]), "=r"(r[2]), "=r"(r[3]) : "r"(saddr));
}
__device__ __forceinline__ void cp16(uint32_t dst, const void* src) {
    asm volatile("cp.async.cg.shared.global [%0], [%1], 16;\n" :: "r"(dst), "l"(src));
}
__device__ __forceinline__ void cp_commit() {
    asm volatile("cp.async.commit_group;\n");
}
template<int N>
__device__ __forceinline__ void cp_wait() {
    asm volatile("cp.async.wait_group %0;\n" :: "n"(N));
}
__device__ __forceinline__ float sigf(float x) { return 1.f / (1.f + expf(-x)); }

struct GP {
    const uint32_t *A, *A1, *A2;   // tf32 bit sources
    const uint32_t *B0;            // packed tf32 weights
    const float *bias0, *bias1;
    const float *cell;
    float *out0, *out1;
    uint32_t *outT;                // tf32 mirror output (MODE 0/2)
};

// MODE 0: encoder  x = relu(moT @ WencT^T + b)          N=256 K=128
// MODE 1: qkv      {q,k,v} = x @ WqkvT^T (+b,relu v)    N=64  K=256 (bx picks W)
// MODE 2: gates    [moT|eT|hidT] @ wcatT^T + LSTM       N=1024 K=448
// MODE 3: decoder  m_act = hT @ WdecT^T + b             N=32  K=256
template<int MODE>
__global__ void __launch_bounds__(256, 2) gemm_tf32(GP p) {
    constexpr int BN = (MODE == 1) ? 64 : (MODE == 3) ? 32 : 128;
    constexpr int WC = (MODE == 1) ? 2  : (MODE == 3) ? 1  : 4;
    constexpr int WR = 8 / WC;
    constexpr int MT = 8 / WR;           // m16 tiles per warp
    constexpr int NT = 4;                // n8 tiles per warp
    constexpr int K  = (MODE == 0) ? 128 : (MODE == 2) ? 448 : 256;
    constexpr int ITERS = K / 16;
    constexpr int WTM = MT * 16;
    constexpr int S   = 3;               // pipeline stages
    constexpr int AK  = (MODE == 0) ? 128 : 256;       // A row stride (simple modes)
    constexpr int BKW = K;                              // B row stride words
    constexpr uint32_t ASTAGE_B = 128 * 20 * 4;         // 10240 bytes
    constexpr uint32_t BSTAGE_B = BN * 20 * 4;

    extern __shared__ uint32_t smem_u[];
    const uint32_t As_sh = (uint32_t)__cvta_generic_to_shared(smem_u);
    const uint32_t Bs_sh = As_sh + S * ASTAGE_B;

    const int tid  = threadIdx.x;
    const int lane = tid & 31, warp = tid >> 5;
    const int wr = warp / WC, wc = warp % WC;
    const int q  = lane & 3,  rr = lane >> 2;
    const int m0 = blockIdx.y * 128;
    const int bx = blockIdx.x;

    const int arow = tid >> 2;          // 0..63
    const int akc  = (tid & 3) * 4;     // 0,4,8,12
    const uint32_t tOff = 4u * (arow * 20 + akc);

    // per-thread source base pointers (k = akc folded in)
    const uint32_t *pA = nullptr, *pMo = nullptr, *pE = nullptr, *pHid = nullptr;
    if constexpr (MODE == 2) {
        pMo  = p.A  + (size_t)(m0 + arow) * 128 + akc;
        pE   = p.A1 + (size_t)(m0 + arow) * 64  + akc;
        pHid = p.A2 + (size_t)(m0 + arow) * 256 + akc;
    } else {
        pA = p.A + (size_t)(m0 + arow) * AK + akc;
    }
    const uint32_t* pB;
    if constexpr (MODE == 0)      pB = p.B0 + (size_t)(bx * 128 + arow) * 128 + akc;
    else if constexpr (MODE == 1) pB = p.B0 + (size_t)(bx * 64 + arow) * 256 + akc;
    else if constexpr (MODE == 2) pB = p.B0 + (size_t)(bx * 128 + arow) * 448 + akc;
    else                          pB = p.B0 + (size_t)arow * 256 + akc;

    auto issue = [&](int it, int s) {
        uint32_t ad = As_sh + (uint32_t)s * ASTAGE_B + tOff;
        uint32_t bd = Bs_sh + (uint32_t)s * BSTAGE_B + tOff;
        const uint32_t *a0, *a1;
        if constexpr (MODE == 2) {
            if (it < 8)       { a0 = pMo + it * 16;          a1 = a0 + 64 * 128; }
            else if (it < 12) { a0 = pE + (it * 16 - 128);   a1 = a0 + 64 * 64; }
            else              { a0 = pHid + (it * 16 - 192); a1 = a0 + 64 * 256; }
        } else {
            a0 = pA + it * 16; a1 = a0 + 64 * AK;
        }
        cp16(ad, a0);
        cp16(ad + 64 * 80, a1);
        if constexpr (BN == 128) {
            cp16(bd, pB + it * 16);
            cp16(bd + 64 * 80, pB + (size_t)64 * BKW + it * 16);
        } else if constexpr (BN == 64) {
            cp16(bd, pB + it * 16);
        } else {
            if (tid < 128) cp16(bd, pB + it * 16);
        }
    };

    float acc[MT][NT][4];
    #pragma unroll
    for (int i = 0; i < MT; i++)
        #pragma unroll
        for (int j = 0; j < NT; j++)
            #pragma unroll
            for (int t = 0; t < 4; t++) acc[i][j][t] = 0.f;

    // ldmatrix lane addressing
    const int a_r = lane & 15, a_h = lane >> 4;
    const int b_g = lane >> 3, b_rl = lane & 7;
    const int b_row = (b_g >> 1) * 8 + b_rl;
    const int b_k4  = (b_g & 1) * 4;

    issue(0, 0); cp_commit();
    issue(1, 1); cp_commit();

    int s = 0, s2 = 2;   // current compute stage, stage to fill (it+2)
    for (int it = 0; it < ITERS; ++it) {
        cp_wait<1>();
        __syncthreads();
        if (it + 2 < ITERS) issue(it + 2, s2);
        cp_commit();

        const uint32_t Ab = As_sh + (uint32_t)s * ASTAGE_B;
        const uint32_t Bb = Bs_sh + (uint32_t)s * BSTAGE_B;
        #pragma unroll
        for (int ph = 0; ph < 2; ++ph) {
            uint32_t af[MT][4], bf[NT][2];
            #pragma unroll
            for (int mi = 0; mi < MT; ++mi)
                ldsm4(af[mi], Ab + 4u * ((wr * WTM + mi * 16 + a_r) * 20 + ph * 8 + a_h * 4));
            #pragma unroll
            for (int pi = 0; pi < NT / 2; ++pi)
                ldsm4(&bf[2 * pi][0], Bb + 4u * ((wc * 32 + pi * 16 + b_row) * 20 + ph * 8 + b_k4));
            #pragma unroll
            for (int mi = 0; mi < MT; ++mi)
                #pragma unroll
                for (int ni = 0; ni < NT; ++ni)
                    mma8(acc[mi][ni], af[mi], bf[ni]);
        }
        if (++s == S) s = 0;
        if (++s2 == S) s2 = 0;
    }
    __syncthreads();   // mainloop smem reads done before any epilogue smem reuse

    // ---------------- epilogues ----------------
    if constexpr (MODE == 0) {
        #pragma unroll
        for (int mi = 0; mi < MT; ++mi)
            #pragma unroll
            for (int ni = 0; ni < NT; ++ni) {
                int n = bx * 128 + wc * 32 + ni * 8 + q * 2;
                int m = m0 + wr * WTM + mi * 16 + rr;
                float b0v = p.bias0[n], b1v = p.bias0[n + 1];
                uint2 v0 = make_uint2(f2tf(fmaxf(acc[mi][ni][0] + b0v, 0.f)),
                                      f2tf(fmaxf(acc[mi][ni][1] + b1v, 0.f)));
                uint2 v1 = make_uint2(f2tf(fmaxf(acc[mi][ni][2] + b0v, 0.f)),
                                      f2tf(fmaxf(acc[mi][ni][3] + b1v, 0.f)));
                *(uint2*)(p.outT + (size_t)m * 256 + n) = v0;
                *(uint2*)(p.outT + (size_t)(m + 8) * 256 + n) = v1;
            }
    } else if constexpr (MODE == 1) {
        float* o = (bx == 0) ? p.out0 : (bx == 1) ? p.out1 : (float*)p.outT;
        bool act = (bx == 2);
        #pragma unroll
        for (int mi = 0; mi < MT; ++mi)
            #pragma unroll
            for (int ni = 0; ni < NT; ++ni) {
                int n = wc * 32 + ni * 8 + q * 2;
                int m = m0 + wr * WTM + mi * 16 + rr;
                float b0v = act ? p.bias0[n] : 0.f, b1v = act ? p.bias0[n + 1] : 0.f;
                float v0 = acc[mi][ni][0] + b0v, v1 = acc[mi][ni][1] + b1v;
                float v2 = acc[mi][ni][2] + b0v, v3 = acc[mi][ni][3] + b1v;
                if (act) { v0 = fmaxf(v0, 0.f); v1 = fmaxf(v1, 0.f); v2 = fmaxf(v2, 0.f); v3 = fmaxf(v3, 0.f); }
                *(float2*)(o + (size_t)m * 64 + n) = make_float2(v0, v1);
                *(float2*)(o + (size_t)(m + 8) * 64 + n) = make_float2(v2, v3);
            }
    } else if constexpr (MODE == 3) {
        #pragma unroll
        for (int mi = 0; mi < MT; ++mi)
            #pragma unroll
            for (int ni = 0; ni < NT; ++ni) {
                int n = ni * 8 + q * 2;
                int m = m0 + wr * WTM + mi * 16 + rr;
                float b0v = p.bias0[n], b1v = p.bias0[n + 1];
                *(float2*)(p.out0 + (size_t)m * 32 + n) =
                    make_float2(acc[mi][ni][0] + b0v, acc[mi][ni][1] + b1v);
                *(float2*)(p.out0 + (size_t)(m + 8) * 32 + n) =
                    make_float2(acc[mi][ni][2] + b0v, acc[mi][ni][3] + b1v);
            }
    } else {
        // MODE 2: fused LSTM epilogue. Columns n = h_local*4 + gate (i,f,g,o)
        float* smc = (float*)smem_u;            // cell tile [128][33]
        float* smr = smc + 128 * 33;            // h tile   [128][33]
        const int h0 = bx * 32;
        for (int i = tid; i < 4096; i += 256) {
            int m = i >> 5, h = i & 31;
            smc[m * 33 + h] = p.cell[(size_t)(m0 + m) * 256 + h0 + h];
        }
        __syncthreads();

        const bool even = (q & 1) == 0;
        #pragma unroll
        for (int ni = 0; ni < NT; ++ni) {
            int nb = wc * 32 + ni * 8;
            int h_loc = (nb >> 2) + (q >> 1);
            int hg = h0 + h_loc;
            int g0 = (q & 1) * 2;
            float bb0 = p.bias0[g0 * 256 + hg] + p.bias1[g0 * 256 + hg];
            float bb1 = p.bias0[(g0 + 1) * 256 + hg] + p.bias1[(g0 + 1) * 256 + hg];
            #pragma unroll
            for (int mi = 0; mi < MT; ++mi) {
                float c0 = acc[mi][ni][0] + bb0, c1 = acc[mi][ni][1] + bb1;
                float c2 = acc[mi][ni][2] + bb0, c3 = acc[mi][ni][3] + bb1;
                float p0 = __shfl_xor_sync(~0u, c0, 1);
                float p1 = __shfl_xor_sync(~0u, c1, 1);
                float p2 = __shfl_xor_sync(~0u, c2, 1);
                float p3 = __shfl_xor_sync(~0u, c3, 1);
                if (even) {
                    int ml = wr * 64 + mi * 16 + rr;
                    float cp0 = smc[ml * 33 + h_loc];
                    float cp1 = smc[(ml + 8) * 33 + h_loc];
                    float cn0 = sigf(c1) * cp0 + sigf(c0) * tanhf(p0);
                    float hn0 = sigf(p1) * tanhf(cn0);
                    float cn1 = sigf(c3) * cp1 + sigf(c2) * tanhf(p2);
                    float hn1 = sigf(p3) * tanhf(cn1);
                    acc[mi][ni][0] = hn0; acc[mi][ni][1] = cn0;
                    acc[mi][ni][2] = hn1; acc[mi][ni][3] = cn1;
                }
            }
        }
        __syncthreads();
        #pragma unroll
        for (int ni = 0; ni < NT; ++ni) {
            int nb = wc * 32 + ni * 8;
            int h_loc = (nb >> 2) + (q >> 1);
            #pragma unroll
            for (int mi = 0; mi < MT; ++mi) {
                if (even) {
                    int ml = wr * 64 + mi * 16 + rr;
                    smr[ml * 33 + h_loc]       = acc[mi][ni][0];
                    smc[ml * 33 + h_loc]       = acc[mi][ni][1];
                    smr[(ml + 8) * 33 + h_loc] = acc[mi][ni][2];
                    smc[(ml + 8) * 33 + h_loc] = acc[mi][ni][3];
                }
            }
        }
        __syncthreads();
        for (int i = tid; i < 4096; i += 256) {
            int m = i >> 5, h = i & 31;
            size_t off = (size_t)(m0 + m) * 256 + h0 + h;
            float hv = smr[m * 33 + h];
            p.out0[off] = hv;
            p.out1[off] = smc[m * 33 + h];
            p.outT[off] = f2tf(hv);
        }
    }
}

// ---------------- pack/convert prologue -------------------------------------
__global__ void pack_kernel(const float* __restrict__ mo, const float* __restrict__ hid,
                            const float* __restrict__ Wenc,
                            const float* __restrict__ Wq, const float* __restrict__ Wk,
                            const float* __restrict__ Wv,
                            const float* __restrict__ Wih, const float* __restrict__ Whh,
                            const float* __restrict__ Wdec,
                            uint32_t* __restrict__ moT, uint32_t* __restrict__ hidT,
                            uint32_t* __restrict__ wencT, uint32_t* __restrict__ wqkvT,
                            uint32_t* __restrict__ wcatT, uint32_t* __restrict__ wdecT)
{
    const int stride = gridDim.x * blockDim.x;
    const int g = blockIdx.x * blockDim.x + threadIdx.x;
    for (size_t i = g; i < (size_t)NB * 128; i += stride) moT[i]  = f2tf(mo[i]);
    for (size_t i = g; i < (size_t)NB * 256; i += stride) hidT[i] = f2tf(hid[i]);
    for (int i = g; i < 256 * 128; i += stride) wencT[i] = f2tf(Wenc[i]);
    for (int i = g; i < 64 * 256; i += stride) {
        wqkvT[i]         = f2tf(Wq[i]);
        wqkvT[16384 + i] = f2tf(Wk[i]);
        wqkvT[32768 + i] = f2tf(Wv[i]);
    }
    for (int i = g; i < 1024 * 448; i += stride) {
        int n = i / 448, k = i - n * 448;
        int h = n >> 2, gg = n & 3, r = gg * 256 + h;
        float v = (k < 192) ? Wih[(size_t)r * 192 + k] : Whh[(size_t)r * 256 + (k - 192)];
        wcatT[i] = f2tf(v);
    }
    for (int i = g; i < 32 * 256; i += stride) wdecT[i] = f2tf(Wdec[i]);
}

// ---------------- attention --------------------------------------------------
__global__ __launch_bounds__(128) void attn_kernel(
    const float* __restrict__ Q, const float* __restrict__ Kk,
    const float* __restrict__ V, uint32_t* __restrict__ E)
{
    __shared__ float sq[4][8][68];
    __shared__ float sk[4][8][68];
    __shared__ float sv[4][8][68];

    const int warp = threadIdx.x >> 5;
    const int lane = threadIdx.x & 31;
    const int g    = blockIdx.x * 4 + warp;
    const size_t base = (size_t)g * 8 * A_DIM;

    for (int idx = lane; idx < 128; idx += 32) {
        int i  = idx >> 4;
        int a4 = (idx & 15) * 4;
        float4 t;
        t = *(const float4*)(Q + base + i * A_DIM + a4);
        sq[warp][i][a4+0]=t.x; sq[warp][i][a4+1]=t.y; sq[warp][i][a4+2]=t.z; sq[warp][i][a4+3]=t.w;
        t = *(const float4*)(Kk + base + i * A_DIM + a4);
        sk[warp][i][a4+0]=t.x; sk[warp][i][a4+1]=t.y; sk[warp][i][a4+2]=t.z; sk[warp][i][a4+3]=t.w;
        t = *(const float4*)(V + base + i * A_DIM + a4);
        sv[warp][i][a4+0]=t.x; sv[warp][i][a4+1]=t.y; sv[warp][i][a4+2]=t.z; sv[warp][i][a4+3]=t.w;
    }
    __syncwarp();

    const int j  = lane & 7;
    const int i0 = lane >> 3;
    const int i1 = i0 + 4;

    float s0 = 0.f, s1 = 0.f;
    #pragma unroll
    for (int a = 0; a < A_DIM; a++) {
        float kv = sk[warp][j][a];
        s0 = fmaf(sq[warp][i0][a], kv, s0);
        s1 = fmaf(sq[warp][i1][a], kv, s1);
    }
    s0 *= 0.125f; s1 *= 0.125f;
    if (i0 == j) s0 = -1e9f;
    if (i1 == j) s1 = -1e9f;

    const unsigned fm = 0xffffffffu;
    float m0 = s0, m1 = s1;
    #pragma unroll
    for (int o = 4; o >= 1; o >>= 1) {
        m0 = fmaxf(m0, __shfl_xor_sync(fm, m0, o));
        m1 = fmaxf(m1, __shfl_xor_sync(fm, m1, o));
    }
    float e0 = expf(s0 - m0), e1 = expf(s1 - m1);
    float z0 = e0, z1 = e1;
    #pragma unroll
    for (int o = 4; o >= 1; o >>= 1) {
        z0 += __shfl_xor_sync(fm, z0, o);
        z1 += __shfl_xor_sync(fm, z1, o);
    }
    float w0 = e0 / z0, w1 = e1 / z1;

    float accv[8][2] = {};
    #pragma unroll
    for (int i = 0; i < 8; i++) {
        #pragma unroll
        for (int jj = 0; jj < 8; jj++) {
            float wij = __shfl_sync(fm, (i < 4) ? w0 : w1, ((i & 3) << 3) + jj);
            accv[i][0] = fmaf(wij, sv[warp][jj][lane],      accv[i][0]);
            accv[i][1] = fmaf(wij, sv[warp][jj][lane + 32], accv[i][1]);
        }
    }
    #pragma unroll
    for (int i = 0; i < 8; i++) {
        uint32_t* er = E + base + (size_t)i * A_DIM;
        er[lane]      = f2tf(accv[i][0]);
        er[lane + 32] = f2tf(accv[i][1]);
    }
}

// ---------------- launch ----------------------------------------------------
extern "C" void kernel_launch(void* const* d_in, const int* in_sizes, int n_in,
                              void* d_out, int out_size)
{
    const float* mo    = (const float*)d_in[0];
    const float* hid   = (const float*)d_in[1];
    const float* cell  = (const float*)d_in[2];
    const float* Wenc  = (const float*)d_in[3];
    const float* benc  = (const float*)d_in[4];
    const float* Wq    = (const float*)d_in[5];
    const float* Wk    = (const float*)d_in[6];
    const float* Wv    = (const float*)d_in[7];
    const float* bv    = (const float*)d_in[8];
    const float* Wih   = (const float*)d_in[9];
    const float* Whh   = (const float*)d_in[10];
    const float* bih   = (const float*)d_in[11];
    const float* bhh   = (const float*)d_in[12];
    const float* Wdec  = (const float*)d_in[13];
    const float* bdec  = (const float*)d_in[14];

    float* out   = (float*)d_out;
    float* m_act = out;
    float* h_out = out + (size_t)NB * NA_DIM;
    float* c_out = h_out + (size_t)NB * H_DIM;

    uint32_t *moT, *hidT, *x, *eT, *hT, *wencT, *wqkvT, *wcatT, *wdecT;
    float *q, *k, *v;
    cudaGetSymbolAddress((void**)&moT,   g_moT);
    cudaGetSymbolAddress((void**)&hidT,  g_hidT);
    cudaGetSymbolAddress((void**)&x,     g_x);
    cudaGetSymbolAddress((void**)&q,     g_q);
    cudaGetSymbolAddress((void**)&k,     g_k);
    cudaGetSymbolAddress((void**)&v,     g_v);
    cudaGetSymbolAddress((void**)&eT,    g_eT);
    cudaGetSymbolAddress((void**)&hT,    g_hT);
    cudaGetSymbolAddress((void**)&wencT, g_wencT);
    cudaGetSymbolAddress((void**)&wqkvT, g_wqkvT);
    cudaGetSymbolAddress((void**)&wcatT, g_wcatT);
    cudaGetSymbolAddress((void**)&wdecT, g_wdecT);

    // opt-in dynamic smem (>48KB) — attribute set, not allocation
    cudaFuncSetAttribute(gemm_tf32<0>, cudaFuncAttributeMaxDynamicSharedMemorySize, 61440);
    cudaFuncSetAttribute(gemm_tf32<1>, cudaFuncAttributeMaxDynamicSharedMemorySize, 46080);
    cudaFuncSetAttribute(gemm_tf32<2>, cudaFuncAttributeMaxDynamicSharedMemorySize, 61440);
    cudaFuncSetAttribute(gemm_tf32<3>, cudaFuncAttributeMaxDynamicSharedMemorySize, 38400);

    // 0) pack + convert
    pack_kernel<<<2048, 256>>>(mo, hid, Wenc, Wq, Wk, Wv, Wih, Whh, Wdec,
                               moT, hidT, wencT, wqkvT, wcatT, wdecT);
    // 1) encoder
    {
        GP p{}; p.A = moT; p.B0 = wencT; p.bias0 = benc; p.outT = x;
        gemm_tf32<0><<<dim3(2, 1024), 256, 61440>>>(p);
    }
    // 2) q,k,v
    {
        GP p{}; p.A = x; p.B0 = wqkvT; p.bias0 = bv;
        p.out0 = q; p.out1 = k; p.outT = (uint32_t*)v;
        gemm_tf32<1><<<dim3(3, 1024), 256, 46080>>>(p);
    }
    // 3) attention
    attn_kernel<<<NBAT / 4, 128>>>(q, k, v, eT);
    // 4) gates GEMM + fused LSTM
    {
        GP p{}; p.A = moT; p.A1 = eT; p.A2 = hidT;
        p.B0 = wcatT; p.bias0 = bih; p.bias1 = bhh;
        p.cell = cell; p.out0 = h_out; p.out1 = c_out; p.outT = hT;
        gemm_tf32<2><<<dim3(8, 1024), 256, 61440>>>(p);
    }
    // 5) decoder
    {
        GP p{}; p.A = hT; p.B0 = wdecT; p.bias0 = bdec; p.out0 = m_act;
        gemm_tf32<3><<<dim3(1, 1024), 256, 38400>>>(p);
    }
}

// round 7
// speedup vs baseline: 4.2470x; 1.3369x over previous
#include <cuda_runtime.h>
#include <cuda_fp16.h>
#include <math.h>
#include <stdint.h>

// Problem constants
#define NBAT   16384
#define NMAST  8
#define NB     (NBAT * NMAST)   // 131072
#define IN_DIM 128
#define H_DIM  256
#define A_DIM  64
#define NA_DIM 32

// ---------------- scratch ----------------------------------------------------
__device__ uint16_t g_moH [(size_t)NB * IN_DIM];
__device__ uint16_t g_hidH[(size_t)NB * H_DIM];
__device__ uint16_t g_xH  [(size_t)NB * H_DIM];   // encoder out, fp16
__device__ float    g_q   [(size_t)NB * A_DIM];
__device__ float    g_k   [(size_t)NB * A_DIM];
__device__ float    g_v   [(size_t)NB * A_DIM];
__device__ uint16_t g_eH  [(size_t)NB * A_DIM];   // attention out, fp16
__device__ uint16_t g_hH  [(size_t)NB * H_DIM];   // h_out copy, fp16
__device__ uint16_t g_wencH[256 * 128];
__device__ uint16_t g_wqkvH[3 * 64 * 256];
__device__ uint16_t g_wcatH[1024 * 448];          // gate-interleaved [h*4+g][448]
__device__ uint16_t g_wdecH[32 * 256];

// ---------------- helpers ----------------------------------------------------
__device__ __forceinline__ uint16_t f2h(float f) {
    return __half_as_ushort(__float2half_rn(f));
}
__device__ __forceinline__ void mma16(float* c, const uint32_t* a, const uint32_t* b) {
    asm volatile(
        "mma.sync.aligned.m16n8k16.row.col.f32.f16.f16.f32 "
        "{%0,%1,%2,%3},{%4,%5,%6,%7},{%8,%9},{%0,%1,%2,%3};\n"
        : "+f"(c[0]), "+f"(c[1]), "+f"(c[2]), "+f"(c[3])
        : "r"(a[0]), "r"(a[1]), "r"(a[2]), "r"(a[3]), "r"(b[0]), "r"(b[1]));
}
__device__ __forceinline__ void ldsm4(uint32_t* r, uint32_t saddr) {
    asm volatile("ldmatrix.sync.aligned.m8n8.x4.shared.b16 {%0,%1,%2,%3}, [%4];"
        : "=r"(r[0]), "=r"(r[1]), "=r"(r[2]), "=r"(r[3]) : "r"(saddr));
}
__device__ __forceinline__ void cp16(uint32_t dst, const void* src) {
    asm volatile("cp.async.cg.shared.global [%0], [%1], 16;\n" :: "r"(dst), "l"(src));
}
__device__ __forceinline__ void cp_commit() {
    asm volatile("cp.async.commit_group;\n");
}
template<int N>
__device__ __forceinline__ void cp_wait() {
    asm volatile("cp.async.wait_group %0;\n" :: "n"(N));
}
__device__ __forceinline__ float sigf(float x) { return 1.f / (1.f + expf(-x)); }

struct GP {
    const uint16_t *A, *A1, *A2;   // fp16 sources
    const uint16_t *B0;            // packed fp16 weights
    const float *bias0, *bias1;
    const float *cell;
    float *out0, *out1, *out2;
    uint16_t *outH;                // fp16 mirror output
};

// MODE 0: encoder  x = relu(moH @ WencH^T + b)      N=256  K=128
// MODE 1: qkv      {q,k,v} = xH @ W^T (+b,relu v)   N=64   K=256 (bx picks W)
// MODE 2: gates    [moH|eH|hidH] @ wcatH^T + LSTM   N=1024 K=448
// MODE 3: decoder  m_act = hH @ WdecH^T + b         N=32   K=256
template<int MODE>
__global__ void __launch_bounds__(256, 2) gemm_f16(GP p) {
    constexpr int BN = (MODE == 1) ? 64 : (MODE == 3) ? 32 : 128;
    constexpr int WC = (MODE == 1) ? 2  : (MODE == 3) ? 1  : 4;
    constexpr int WR = 8 / WC;
    constexpr int MT = 8 / WR;           // m16 tiles per warp
    constexpr int NT = 4;                // n8 tiles per warp
    constexpr int K  = (MODE == 0) ? 128 : (MODE == 2) ? 448 : 256;
    constexpr int ITERS = K / 32;        // 32 halves (64B) per k-chunk
    constexpr int WTM = MT * 16;
    constexpr int S   = 3;
    constexpr int AK  = (MODE == 0) ? 128 : 256;   // A row stride halves (simple modes)
    constexpr int BKH = K;                          // B row stride halves
    constexpr uint32_t ASTAGE_B = 128 * 80;        // 80B padded rows
    constexpr uint32_t BSTAGE_B = BN * 80;

    extern __shared__ uint32_t smem_u[];
    const uint32_t As_sh = (uint32_t)__cvta_generic_to_shared(smem_u);
    const uint32_t Bs_sh = As_sh + S * ASTAGE_B;

    const int tid  = threadIdx.x;
    const int lane = tid & 31, warp = tid >> 5;
    const int wr = warp / WC, wc = warp % WC;
    const int q  = lane & 3,  rr = lane >> 2;
    const int m0 = blockIdx.y * 128;
    const int bx = blockIdx.x;

    // load mapping: each 16B task = 8 halves; row has 4 segs (32 halves = 64B)
    const int arow = tid >> 2;          // 0..63
    const int aseg = tid & 3;           // 0..3
    const uint32_t tOff = (uint32_t)(arow * 80 + aseg * 16);

    const uint16_t* pA = p.A + (size_t)(m0 + arow) * AK + aseg * 8;  // simple modes
    const uint16_t* pB;
    if constexpr (MODE == 0)      pB = p.B0 + (size_t)(bx * 128 + arow) * 128 + aseg * 8;
    else if constexpr (MODE == 1) pB = p.B0 + (size_t)(bx * 64 + arow) * 256 + aseg * 8;
    else if constexpr (MODE == 2) pB = p.B0 + (size_t)(bx * 128 + arow) * 448 + aseg * 8;
    else                          pB = p.B0 + (size_t)arow * 256 + aseg * 8;

    auto issue = [&](int it, int s) {
        uint32_t ad = As_sh + (uint32_t)s * ASTAGE_B + tOff;
        uint32_t bd = Bs_sh + (uint32_t)s * BSTAGE_B + tOff;
        if constexpr (MODE == 2) {
            const uint16_t *a0, *a1;
            int kh = it * 32 + aseg * 8;
            if (it < 4)      { a0 = p.A  + (size_t)(m0 + arow) * 128 + kh;
                               a1 = a0 + (size_t)64 * 128; }
            else if (it < 6) { a0 = p.A1 + (size_t)(m0 + arow) * 64 + (kh - 128);
                               a1 = a0 + (size_t)64 * 64; }
            else             { a0 = p.A2 + (size_t)(m0 + arow) * 256 + (kh - 192);
                               a1 = a0 + (size_t)64 * 256; }
            cp16(ad, a0);
            cp16(ad + 64 * 80, a1);
        } else {
            const uint16_t* a0 = pA + it * 32;
            cp16(ad, a0);
            cp16(ad + 64 * 80, a0 + (size_t)64 * AK);
        }
        if constexpr (BN == 128) {
            cp16(bd, pB + it * 32);
            cp16(bd + 64 * 80, pB + (size_t)64 * BKH + it * 32);
        } else if constexpr (BN == 64) {
            cp16(bd, pB + it * 32);
        } else {
            if (tid < 128) cp16(bd, pB + it * 32);
        }
    };

    float acc[MT][NT][4];
    #pragma unroll
    for (int i = 0; i < MT; i++)
        #pragma unroll
        for (int j = 0; j < NT; j++)
            #pragma unroll
            for (int t = 0; t < 4; t++) acc[i][j][t] = 0.f;

    // ldmatrix lane addressing
    const int a_r = lane & 15, a_h = lane >> 4;       // A: 16 rows, k halves split
    const int b_g = lane >> 3, b_rl = lane & 7;       // B: 4 groups of 8 lanes
    const int b_row = (b_g >> 1) * 8 + b_rl;
    const int b_k16 = (b_g & 1) * 16;                 // byte offset for k8..15

    issue(0, 0); cp_commit();
    issue(1, 1); cp_commit();

    int s = 0, s2 = 2;
    for (int it = 0; it < ITERS; ++it) {
        cp_wait<1>();
        __syncthreads();
        if (it + 2 < ITERS) issue(it + 2, s2);
        cp_commit();

        const uint32_t Ab = As_sh + (uint32_t)s * ASTAGE_B;
        const uint32_t Bb = Bs_sh + (uint32_t)s * BSTAGE_B;
        #pragma unroll
        for (int ph = 0; ph < 2; ++ph) {              // two k16 steps per chunk
            uint32_t af[MT][4], bf[NT][2];
            #pragma unroll
            for (int mi = 0; mi < MT; ++mi)
                ldsm4(af[mi], Ab + (uint32_t)((wr * WTM + mi * 16 + a_r) * 80
                                              + ph * 32 + a_h * 16));
            #pragma unroll
            for (int pi = 0; pi < NT / 2; ++pi)
                ldsm4(&bf[2 * pi][0], Bb + (uint32_t)((wc * 32 + pi * 16 + b_row) * 80
                                                      + ph * 32 + b_k16));
            #pragma unroll
            for (int mi = 0; mi < MT; ++mi)
                #pragma unroll
                for (int ni = 0; ni < NT; ++ni)
                    mma16(acc[mi][ni], af[mi], bf[ni]);
        }
        if (++s == S) s = 0;
        if (++s2 == S) s2 = 0;
    }
    __syncthreads();

    // ---------------- epilogues ----------------
    if constexpr (MODE == 0) {
        #pragma unroll
        for (int mi = 0; mi < MT; ++mi)
            #pragma unroll
            for (int ni = 0; ni < NT; ++ni) {
                int n = bx * 128 + wc * 32 + ni * 8 + q * 2;
                int m = m0 + wr * WTM + mi * 16 + rr;
                float b0v = p.bias0[n], b1v = p.bias0[n + 1];
                __half2 h0 = __floats2half2_rn(fmaxf(acc[mi][ni][0] + b0v, 0.f),
                                               fmaxf(acc[mi][ni][1] + b1v, 0.f));
                __half2 h1 = __floats2half2_rn(fmaxf(acc[mi][ni][2] + b0v, 0.f),
                                               fmaxf(acc[mi][ni][3] + b1v, 0.f));
                *(__half2*)(p.outH + (size_t)m * 256 + n) = h0;
                *(__half2*)(p.outH + (size_t)(m + 8) * 256 + n) = h1;
            }
    } else if constexpr (MODE == 1) {
        float* o = (bx == 0) ? p.out0 : (bx == 1) ? p.out1 : p.out2;
        bool act = (bx == 2);
        #pragma unroll
        for (int mi = 0; mi < MT; ++mi)
            #pragma unroll
            for (int ni = 0; ni < NT; ++ni) {
                int n = wc * 32 + ni * 8 + q * 2;
                int m = m0 + wr * WTM + mi * 16 + rr;
                float b0v = act ? p.bias0[n] : 0.f, b1v = act ? p.bias0[n + 1] : 0.f;
                float v0 = acc[mi][ni][0] + b0v, v1 = acc[mi][ni][1] + b1v;
                float v2 = acc[mi][ni][2] + b0v, v3 = acc[mi][ni][3] + b1v;
                if (act) { v0 = fmaxf(v0, 0.f); v1 = fmaxf(v1, 0.f); v2 = fmaxf(v2, 0.f); v3 = fmaxf(v3, 0.f); }
                *(float2*)(o + (size_t)m * 64 + n) = make_float2(v0, v1);
                *(float2*)(o + (size_t)(m + 8) * 64 + n) = make_float2(v2, v3);
            }
    } else if constexpr (MODE == 3) {
        #pragma unroll
        for (int mi = 0; mi < MT; ++mi)
            #pragma unroll
            for (int ni = 0; ni < NT; ++ni) {
                int n = ni * 8 + q * 2;
                int m = m0 + wr * WTM + mi * 16 + rr;
                float b0v = p.bias0[n], b1v = p.bias0[n + 1];
                *(float2*)(p.out0 + (size_t)m * 32 + n) =
                    make_float2(acc[mi][ni][0] + b0v, acc[mi][ni][1] + b1v);
                *(float2*)(p.out0 + (size_t)(m + 8) * 32 + n) =
                    make_float2(acc[mi][ni][2] + b0v, acc[mi][ni][3] + b1v);
            }
    } else {
        // MODE 2: fused LSTM epilogue. Columns n = h_local*4 + gate (i,f,g,o)
        float* smc = (float*)smem_u;            // cell tile [128][33]
        float* smr = smc + 128 * 33;            // h tile   [128][33]
        const int h0 = bx * 32;
        for (int i = tid; i < 4096; i += 256) {
            int m = i >> 5, h = i & 31;
            smc[m * 33 + h] = p.cell[(size_t)(m0 + m) * 256 + h0 + h];
        }
        __syncthreads();

        const bool even = (q & 1) == 0;
        #pragma unroll
        for (int ni = 0; ni < NT; ++ni) {
            int nb = wc * 32 + ni * 8;
            int h_loc = (nb >> 2) + (q >> 1);
            int hg = h0 + h_loc;
            int g0 = (q & 1) * 2;
            float bb0 = p.bias0[g0 * 256 + hg] + p.bias1[g0 * 256 + hg];
            float bb1 = p.bias0[(g0 + 1) * 256 + hg] + p.bias1[(g0 + 1) * 256 + hg];
            #pragma unroll
            for (int mi = 0; mi < MT; ++mi) {
                float c0 = acc[mi][ni][0] + bb0, c1 = acc[mi][ni][1] + bb1;
                float c2 = acc[mi][ni][2] + bb0, c3 = acc[mi][ni][3] + bb1;
                float p0 = __shfl_xor_sync(~0u, c0, 1);
                float p1 = __shfl_xor_sync(~0u, c1, 1);
                float p2 = __shfl_xor_sync(~0u, c2, 1);
                float p3 = __shfl_xor_sync(~0u, c3, 1);
                if (even) {
                    // even lane: gates i (c0/c2), f (c1/c3); partner: g (p0/p2), o (p1/p3)
                    int ml = wr * 64 + mi * 16 + rr;
                    float cp0 = smc[ml * 33 + h_loc];
                    float cp1 = smc[(ml + 8) * 33 + h_loc];
                    float cn0 = sigf(c1) * cp0 + sigf(c0) * tanhf(p0);
                    float hn0 = sigf(p1) * tanhf(cn0);
                    float cn1 = sigf(c3) * cp1 + sigf(c2) * tanhf(p2);
                    float hn1 = sigf(p3) * tanhf(cn1);
                    acc[mi][ni][0] = hn0; acc[mi][ni][1] = cn0;
                    acc[mi][ni][2] = hn1; acc[mi][ni][3] = cn1;
                }
            }
        }
        __syncthreads();
        #pragma unroll
        for (int ni = 0; ni < NT; ++ni) {
            int nb = wc * 32 + ni * 8;
            int h_loc = (nb >> 2) + (q >> 1);
            #pragma unroll
            for (int mi = 0; mi < MT; ++mi) {
                if (even) {
                    int ml = wr * 64 + mi * 16 + rr;
                    smr[ml * 33 + h_loc]       = acc[mi][ni][0];
                    smc[ml * 33 + h_loc]       = acc[mi][ni][1];
                    smr[(ml + 8) * 33 + h_loc] = acc[mi][ni][2];
                    smc[(ml + 8) * 33 + h_loc] = acc[mi][ni][3];
                }
            }
        }
        __syncthreads();
        for (int i = tid; i < 4096; i += 256) {
            int m = i >> 5, h = i & 31;
            size_t off = (size_t)(m0 + m) * 256 + h0 + h;
            float hv = smr[m * 33 + h];
            p.out0[off] = hv;
            p.out1[off] = smc[m * 33 + h];
            p.outH[off] = f2h(hv);
        }
    }
}

// ---------------- pack/convert prologue -------------------------------------
__global__ void pack_kernel(const float* __restrict__ mo, const float* __restrict__ hid,
                            const float* __restrict__ Wenc,
                            const float* __restrict__ Wq, const float* __restrict__ Wk,
                            const float* __restrict__ Wv,
                            const float* __restrict__ Wih, const float* __restrict__ Whh,
                            const float* __restrict__ Wdec,
                            uint16_t* __restrict__ moH, uint16_t* __restrict__ hidH,
                            uint16_t* __restrict__ wencH, uint16_t* __restrict__ wqkvH,
                            uint16_t* __restrict__ wcatH, uint16_t* __restrict__ wdecH)
{
    const int stride = gridDim.x * blockDim.x;
    const int g = blockIdx.x * blockDim.x + threadIdx.x;
    for (size_t i = g; i < (size_t)NB * 128; i += stride) moH[i]  = f2h(mo[i]);
    for (size_t i = g; i < (size_t)NB * 256; i += stride) hidH[i] = f2h(hid[i]);
    for (int i = g; i < 256 * 128; i += stride) wencH[i] = f2h(Wenc[i]);
    for (int i = g; i < 64 * 256; i += stride) {
        wqkvH[i]         = f2h(Wq[i]);
        wqkvH[16384 + i] = f2h(Wk[i]);
        wqkvH[32768 + i] = f2h(Wv[i]);
    }
    for (int i = g; i < 1024 * 448; i += stride) {
        int n = i / 448, k = i - n * 448;
        int h = n >> 2, gg = n & 3, r = gg * 256 + h;
        float v = (k < 192) ? Wih[(size_t)r * 192 + k] : Whh[(size_t)r * 256 + (k - 192)];
        wcatH[i] = f2h(v);
    }
    for (int i = g; i < 32 * 256; i += stride) wdecH[i] = f2h(Wdec[i]);
}

// ---------------- attention --------------------------------------------------
__global__ __launch_bounds__(128) void attn_kernel(
    const float* __restrict__ Q, const float* __restrict__ Kk,
    const float* __restrict__ V, uint16_t* __restrict__ E)
{
    __shared__ float sq[4][8][68];
    __shared__ float sk[4][8][68];
    __shared__ float sv[4][8][68];

    const int warp = threadIdx.x >> 5;
    const int lane = threadIdx.x & 31;
    const int g    = blockIdx.x * 4 + warp;
    const size_t base = (size_t)g * 8 * A_DIM;

    for (int idx = lane; idx < 128; idx += 32) {
        int i  = idx >> 4;
        int a4 = (idx & 15) * 4;
        float4 t;
        t = *(const float4*)(Q + base + i * A_DIM + a4);
        sq[warp][i][a4+0]=t.x; sq[warp][i][a4+1]=t.y; sq[warp][i][a4+2]=t.z; sq[warp][i][a4+3]=t.w;
        t = *(const float4*)(Kk + base + i * A_DIM + a4);
        sk[warp][i][a4+0]=t.x; sk[warp][i][a4+1]=t.y; sk[warp][i][a4+2]=t.z; sk[warp][i][a4+3]=t.w;
        t = *(const float4*)(V + base + i * A_DIM + a4);
        sv[warp][i][a4+0]=t.x; sv[warp][i][a4+1]=t.y; sv[warp][i][a4+2]=t.z; sv[warp][i][a4+3]=t.w;
    }
    __syncwarp();

    const int j  = lane & 7;
    const int i0 = lane >> 3;
    const int i1 = i0 + 4;

    float s0 = 0.f, s1 = 0.f;
    #pragma unroll
    for (int a = 0; a < A_DIM; a++) {
        float kv = sk[warp][j][a];
        s0 = fmaf(sq[warp][i0][a], kv, s0);
        s1 = fmaf(sq[warp][i1][a], kv, s1);
    }
    s0 *= 0.125f; s1 *= 0.125f;
    if (i0 == j) s0 = -1e9f;
    if (i1 == j) s1 = -1e9f;

    const unsigned fm = 0xffffffffu;
    float m0 = s0, m1 = s1;
    #pragma unroll
    for (int o = 4; o >= 1; o >>= 1) {
        m0 = fmaxf(m0, __shfl_xor_sync(fm, m0, o));
        m1 = fmaxf(m1, __shfl_xor_sync(fm, m1, o));
    }
    float e0 = expf(s0 - m0), e1 = expf(s1 - m1);
    float z0 = e0, z1 = e1;
    #pragma unroll
    for (int o = 4; o >= 1; o >>= 1) {
        z0 += __shfl_xor_sync(fm, z0, o);
        z1 += __shfl_xor_sync(fm, z1, o);
    }
    float w0 = e0 / z0, w1 = e1 / z1;

    float accv[8][2] = {};
    #pragma unroll
    for (int i = 0; i < 8; i++) {
        #pragma unroll
        for (int jj = 0; jj < 8; jj++) {
            float wij = __shfl_sync(fm, (i < 4) ? w0 : w1, ((i & 3) << 3) + jj);
            accv[i][0] = fmaf(wij, sv[warp][jj][lane],      accv[i][0]);
            accv[i][1] = fmaf(wij, sv[warp][jj][lane + 32], accv[i][1]);
        }
    }
    #pragma unroll
    for (int i = 0; i < 8; i++) {
        uint16_t* er = E + base + (size_t)i * A_DIM;
        er[lane]      = f2h(accv[i][0]);
        er[lane + 32] = f2h(accv[i][1]);
    }
}

// ---------------- launch ----------------------------------------------------
extern "C" void kernel_launch(void* const* d_in, const int* in_sizes, int n_in,
                              void* d_out, int out_size)
{
    const float* mo    = (const float*)d_in[0];
    const float* hid   = (const float*)d_in[1];
    const float* cell  = (const float*)d_in[2];
    const float* Wenc  = (const float*)d_in[3];
    const float* benc  = (const float*)d_in[4];
    const float* Wq    = (const float*)d_in[5];
    const float* Wk    = (const float*)d_in[6];
    const float* Wv    = (const float*)d_in[7];
    const float* bv    = (const float*)d_in[8];
    const float* Wih   = (const float*)d_in[9];
    const float* Whh   = (const float*)d_in[10];
    const float* bih   = (const float*)d_in[11];
    const float* bhh   = (const float*)d_in[12];
    const float* Wdec  = (const float*)d_in[13];
    const float* bdec  = (const float*)d_in[14];

    float* out   = (float*)d_out;
    float* m_act = out;
    float* h_out = out + (size_t)NB * NA_DIM;
    float* c_out = h_out + (size_t)NB * H_DIM;

    uint16_t *moH, *hidH, *xH, *eH, *hH, *wencH, *wqkvH, *wcatH, *wdecH;
    float *q, *k, *v;
    cudaGetSymbolAddress((void**)&moH,   g_moH);
    cudaGetSymbolAddress((void**)&hidH,  g_hidH);
    cudaGetSymbolAddress((void**)&xH,    g_xH);
    cudaGetSymbolAddress((void**)&q,     g_q);
    cudaGetSymbolAddress((void**)&k,     g_k);
    cudaGetSymbolAddress((void**)&v,     g_v);
    cudaGetSymbolAddress((void**)&eH,    g_eH);
    cudaGetSymbolAddress((void**)&hH,    g_hH);
    cudaGetSymbolAddress((void**)&wencH, g_wencH);
    cudaGetSymbolAddress((void**)&wqkvH, g_wqkvH);
    cudaGetSymbolAddress((void**)&wcatH, g_wcatH);
    cudaGetSymbolAddress((void**)&wdecH, g_wdecH);

    cudaFuncSetAttribute(gemm_f16<0>, cudaFuncAttributeMaxDynamicSharedMemorySize, 61440);
    cudaFuncSetAttribute(gemm_f16<1>, cudaFuncAttributeMaxDynamicSharedMemorySize, 46080);
    cudaFuncSetAttribute(gemm_f16<2>, cudaFuncAttributeMaxDynamicSharedMemorySize, 61440);
    cudaFuncSetAttribute(gemm_f16<3>, cudaFuncAttributeMaxDynamicSharedMemorySize, 38400);

    // 0) pack + convert to fp16
    pack_kernel<<<2048, 256>>>(mo, hid, Wenc, Wq, Wk, Wv, Wih, Whh, Wdec,
                               moH, hidH, wencH, wqkvH, wcatH, wdecH);
    // 1) encoder
    {
        GP p{}; p.A = moH; p.B0 = wencH; p.bias0 = benc; p.outH = xH;
        gemm_f16<0><<<dim3(2, 1024), 256, 61440>>>(p);
    }
    // 2) q,k,v
    {
        GP p{}; p.A = xH; p.B0 = wqkvH; p.bias0 = bv;
        p.out0 = q; p.out1 = k; p.out2 = v;
        gemm_f16<1><<<dim3(3, 1024), 256, 46080>>>(p);
    }
    // 3) attention
    attn_kernel<<<NBAT / 4, 128>>>(q, k, v, eH);
    // 4) gates GEMM + fused LSTM
    {
        GP p{}; p.A = moH; p.A1 = eH; p.A2 = hidH;
        p.B0 = wcatH; p.bias0 = bih; p.bias1 = bhh;
        p.cell = cell; p.out0 = h_out; p.out1 = c_out; p.outH = hH;
        gemm_f16<2><<<dim3(8, 1024), 256, 61440>>>(p);
    }
    // 5) decoder
    {
        GP p{}; p.A = hH; p.B0 = wdecH; p.bias0 = bdec; p.out0 = m_act;
        gemm_f16<3><<<dim3(1, 1024), 256, 38400>>>(p);
    }
}

// round 8
// speedup vs baseline: 4.6423x; 1.0931x over previous
#include <cuda_runtime.h>
#include <cuda_fp16.h>
#include <math.h>
#include <stdint.h>

// Problem constants
#define NBAT   16384
#define NMAST  8
#define NB     (NBAT * NMAST)   // 131072
#define IN_DIM 128
#define H_DIM  256
#define A_DIM  64
#define NA_DIM 32

// ---------------- scratch ----------------------------------------------------
__device__ uint16_t g_moH [(size_t)NB * IN_DIM];
__device__ uint16_t g_hidH[(size_t)NB * H_DIM];
__device__ uint16_t g_xH  [(size_t)NB * H_DIM];   // encoder out, fp16
__device__ uint16_t g_eH  [(size_t)NB * A_DIM];   // attention out, fp16
__device__ uint16_t g_hH  [(size_t)NB * H_DIM];   // h_out copy, fp16
__device__ uint16_t g_wencH[256 * 128];
__device__ uint16_t g_wqkvH[3 * 64 * 256];        // [192][256]: q rows 0-63, k 64-127, v 128-191
__device__ uint16_t g_wcatH[1024 * 448];          // gate-interleaved [h*4+g][448]
__device__ uint16_t g_wdecH[32 * 256];

// ---------------- helpers ----------------------------------------------------
__device__ __forceinline__ uint16_t f2h(float f) {
    return __half_as_ushort(__float2half_rn(f));
}
__device__ __forceinline__ void mma16(float* c, const uint32_t* a, const uint32_t* b) {
    asm volatile(
        "mma.sync.aligned.m16n8k16.row.col.f32.f16.f16.f32 "
        "{%0,%1,%2,%3},{%4,%5,%6,%7},{%8,%9},{%0,%1,%2,%3};\n"
        : "+f"(c[0]), "+f"(c[1]), "+f"(c[2]), "+f"(c[3])
        : "r"(a[0]), "r"(a[1]), "r"(a[2]), "r"(a[3]), "r"(b[0]), "r"(b[1]));
}
__device__ __forceinline__ void ldsm4(uint32_t* r, uint32_t saddr) {
    asm volatile("ldmatrix.sync.aligned.m8n8.x4.shared.b16 {%0,%1,%2,%3}, [%4];"
        : "=r"(r[0]), "=r"(r[1]), "=r"(r[2]), "=r"(r[3]) : "r"(saddr));
}
__device__ __forceinline__ void cp16(uint32_t dst, const void* src) {
    asm volatile("cp.async.cg.shared.global [%0], [%1], 16;\n" :: "r"(dst), "l"(src));
}
__device__ __forceinline__ void cp_commit() {
    asm volatile("cp.async.commit_group;\n");
}
template<int N>
__device__ __forceinline__ void cp_wait() {
    asm volatile("cp.async.wait_group %0;\n" :: "n"(N));
}
__device__ __forceinline__ float sigf(float x) { return 1.f / (1.f + expf(-x)); }

struct GP {
    const uint16_t *A, *A1, *A2;   // fp16 sources
    const uint16_t *B0;            // packed fp16 weights
    const float *bias0, *bias1;
    const float *cell;
    float *out0, *out1, *out2;
    uint16_t *outH;                // fp16 mirror output
};

// ============================================================================
// fused QKV GEMM + masked self-attention: one CTA = 128 rows (16 groups)
//   qkv = xH @ wqkv^T  (192 cols: q|k|v), v gets +bv and relu, all fp32 in smem
//   then warp-level attention per group -> eH
// ============================================================================
#define QK_ITERS 8          // K=256 in k32 chunks
#define QK_S 3
#define QK_ASTAGE 10240u    // 128 rows * 80B
#define QK_BSTAGE 15360u    // 192 rows * 80B
#define QK_SMEM 104448u     // 3 * 128*68*4 attention arrays (>= 3*(A+B) stages = 76800)

__global__ void __launch_bounds__(256, 1) qkv_attn_kernel(
    const uint16_t* __restrict__ xH, const uint16_t* __restrict__ wqkvH,
    const float* __restrict__ bv, uint16_t* __restrict__ eH)
{
    extern __shared__ uint32_t smem_u[];
    const uint32_t As_sh = (uint32_t)__cvta_generic_to_shared(smem_u);
    const uint32_t Bs_sh = As_sh + QK_S * QK_ASTAGE;

    const int tid  = threadIdx.x;
    const int lane = tid & 31, warp = tid >> 5;
    const int wr = warp >> 1, wc = warp & 1;     // 4 m-groups x 2 n-groups
    const int qq = lane & 3, rr = lane >> 2;
    const int m0 = blockIdx.x * 128;

    // ldmatrix lane addressing
    const int a_r = lane & 15, a_h = lane >> 4;
    const int b_g = lane >> 3, b_rl = lane & 7;
    const int b_row = (b_g >> 1) * 8 + b_rl;
    const int b_k16 = (b_g & 1) * 16;

    auto issue = [&](int it, int s) {
        uint32_t Ast = As_sh + (uint32_t)s * QK_ASTAGE;
        uint32_t Bst = Bs_sh + (uint32_t)s * QK_BSTAGE;
        #pragma unroll
        for (int t5 = 0; t5 < 5; ++t5) {
            int t = tid + t5 * 256;              // 0..1279
            if (t < 512) {
                int row = t >> 2, seg = t & 3;
                cp16(Ast + (uint32_t)(row * 80 + seg * 16),
                     xH + (size_t)(m0 + row) * 256 + it * 32 + seg * 8);
            } else {
                int u = t - 512;
                int row = u >> 2, seg = u & 3;   // row 0..191
                cp16(Bst + (uint32_t)(row * 80 + seg * 16),
                     wqkvH + (size_t)row * 256 + it * 32 + seg * 8);
            }
        }
    };

    float acc[2][12][4];
    #pragma unroll
    for (int i = 0; i < 2; i++)
        #pragma unroll
        for (int j = 0; j < 12; j++)
            #pragma unroll
            for (int t = 0; t < 4; t++) acc[i][j][t] = 0.f;

    issue(0, 0); cp_commit();
    issue(1, 1); cp_commit();

    int s = 0, s2 = 2;
    for (int it = 0; it < QK_ITERS; ++it) {
        cp_wait<1>();
        __syncthreads();
        if (it + 2 < QK_ITERS) issue(it + 2, s2);
        cp_commit();

        const uint32_t Ab = As_sh + (uint32_t)s * QK_ASTAGE;
        const uint32_t Bb = Bs_sh + (uint32_t)s * QK_BSTAGE;
        #pragma unroll
        for (int ph = 0; ph < 2; ++ph) {
            uint32_t af[2][4], bf[12][2];
            #pragma unroll
            for (int mi = 0; mi < 2; ++mi)
                ldsm4(af[mi], Ab + (uint32_t)((wr * 32 + mi * 16 + a_r) * 80
                                              + ph * 32 + a_h * 16));
            #pragma unroll
            for (int pi = 0; pi < 6; ++pi)
                ldsm4(&bf[2 * pi][0], Bb + (uint32_t)((wc * 96 + pi * 16 + b_row) * 80
                                                      + ph * 32 + b_k16));
            #pragma unroll
            for (int mi = 0; mi < 2; ++mi)
                #pragma unroll
                for (int ni = 0; ni < 12; ++ni)
                    mma16(acc[mi][ni], af[mi], bf[ni]);
        }
        if (++s == QK_S) s = 0;
        if (++s2 == QK_S) s2 = 0;
    }
    cp_wait<0>();
    __syncthreads();   // all stage reads/writes done; smem reused below

    // ---- stage q,k,v (fp32) into smem [128][68] each
    float* sq = (float*)smem_u;
    float* sk = sq + 128 * 68;
    float* sv = sk + 128 * 68;
    #pragma unroll
    for (int mi = 0; mi < 2; ++mi)
        #pragma unroll
        for (int ni = 0; ni < 12; ++ni) {
            int col = wc * 96 + ni * 8 + qq * 2;
            int mat = col >> 6, loc = col & 63;
            int m = wr * 32 + mi * 16 + rr;
            float v0 = acc[mi][ni][0], v1 = acc[mi][ni][1];
            float v2 = acc[mi][ni][2], v3 = acc[mi][ni][3];
            float* dst = (mat == 0) ? sq : (mat == 1) ? sk : sv;
            if (mat == 2) {
                float b0 = bv[loc], b1 = bv[loc + 1];
                v0 = fmaxf(v0 + b0, 0.f); v1 = fmaxf(v1 + b1, 0.f);
                v2 = fmaxf(v2 + b0, 0.f); v3 = fmaxf(v3 + b1, 0.f);
            }
            dst[m * 68 + loc]           = v0;
            dst[m * 68 + loc + 1]       = v1;
            dst[(m + 8) * 68 + loc]     = v2;
            dst[(m + 8) * 68 + loc + 1] = v3;
        }
    __syncthreads();

    // ---- attention: warp w handles groups 2w, 2w+1 (8 rows each)
    const int j  = lane & 7;
    const int i0 = lane >> 3;
    const int i1 = i0 + 4;
    const unsigned fm = 0xffffffffu;
    #pragma unroll
    for (int gi = 0; gi < 2; ++gi) {
        const int r0 = (warp * 2 + gi) * 8;
        float s0 = 0.f, s1 = 0.f;
        #pragma unroll
        for (int a = 0; a < A_DIM; a++) {
            float kv = sk[(r0 + j) * 68 + a];
            s0 = fmaf(sq[(r0 + i0) * 68 + a], kv, s0);
            s1 = fmaf(sq[(r0 + i1) * 68 + a], kv, s1);
        }
        s0 *= 0.125f; s1 *= 0.125f;
        if (i0 == j) s0 = -1e9f;
        if (i1 == j) s1 = -1e9f;

        float mm0 = s0, mm1 = s1;
        #pragma unroll
        for (int o = 4; o >= 1; o >>= 1) {
            mm0 = fmaxf(mm0, __shfl_xor_sync(fm, mm0, o));
            mm1 = fmaxf(mm1, __shfl_xor_sync(fm, mm1, o));
        }
        float e0 = expf(s0 - mm0), e1 = expf(s1 - mm1);
        float z0 = e0, z1 = e1;
        #pragma unroll
        for (int o = 4; o >= 1; o >>= 1) {
            z0 += __shfl_xor_sync(fm, z0, o);
            z1 += __shfl_xor_sync(fm, z1, o);
        }
        float w0 = e0 / z0, w1 = e1 / z1;

        float av[8][2] = {};
        #pragma unroll
        for (int i = 0; i < 8; i++) {
            #pragma unroll
            for (int jj = 0; jj < 8; jj++) {
                float wij = __shfl_sync(fm, (i < 4) ? w0 : w1, ((i & 3) << 3) + jj);
                av[i][0] = fmaf(wij, sv[(r0 + jj) * 68 + lane],      av[i][0]);
                av[i][1] = fmaf(wij, sv[(r0 + jj) * 68 + lane + 32], av[i][1]);
            }
        }
        #pragma unroll
        for (int i = 0; i < 8; i++) {
            uint16_t* er = eH + (size_t)(m0 + r0 + i) * 64;
            er[lane]      = f2h(av[i][0]);
            er[lane + 32] = f2h(av[i][1]);
        }
    }
}

// ============================================================================
// GEMM template: MODE 0 encoder, MODE 2 gates+LSTM, MODE 3 decoder
// ============================================================================
template<int MODE>
__global__ void __launch_bounds__(256, 2) gemm_f16(GP p) {
    constexpr int BN = (MODE == 3) ? 32 : 128;
    constexpr int WC = (MODE == 3) ? 1  : 4;
    constexpr int WR = 8 / WC;
    constexpr int MT = 8 / WR;
    constexpr int NT = 4;
    constexpr int K  = (MODE == 0) ? 128 : (MODE == 2) ? 448 : 256;
    constexpr int ITERS = K / 32;
    constexpr int WTM = MT * 16;
    constexpr int S   = 3;
    constexpr int AK  = (MODE == 0) ? 128 : 256;
    constexpr int BKH = K;
    constexpr uint32_t ASTAGE_B = 128 * 80;
    constexpr uint32_t BSTAGE_B = BN * 80;

    extern __shared__ uint32_t smem_u[];
    const uint32_t As_sh = (uint32_t)__cvta_generic_to_shared(smem_u);
    const uint32_t Bs_sh = As_sh + S * ASTAGE_B;

    const int tid  = threadIdx.x;
    const int lane = tid & 31, warp = tid >> 5;
    const int wr = warp / WC, wc = warp % WC;
    const int q  = lane & 3,  rr = lane >> 2;
    const int m0 = blockIdx.y * 128;
    const int bx = blockIdx.x;

    const int arow = tid >> 2;
    const int aseg = tid & 3;
    const uint32_t tOff = (uint32_t)(arow * 80 + aseg * 16);

    const uint16_t* pA = p.A + (size_t)(m0 + arow) * AK + aseg * 8;
    const uint16_t* pB;
    if constexpr (MODE == 0)      pB = p.B0 + (size_t)(bx * 128 + arow) * 128 + aseg * 8;
    else if constexpr (MODE == 2) pB = p.B0 + (size_t)(bx * 128 + arow) * 448 + aseg * 8;
    else                          pB = p.B0 + (size_t)arow * 256 + aseg * 8;

    auto issue = [&](int it, int s) {
        uint32_t ad = As_sh + (uint32_t)s * ASTAGE_B + tOff;
        uint32_t bd = Bs_sh + (uint32_t)s * BSTAGE_B + tOff;
        if constexpr (MODE == 2) {
            const uint16_t *a0, *a1;
            int kh = it * 32 + aseg * 8;
            if (it < 4)      { a0 = p.A  + (size_t)(m0 + arow) * 128 + kh;
                               a1 = a0 + (size_t)64 * 128; }
            else if (it < 6) { a0 = p.A1 + (size_t)(m0 + arow) * 64 + (kh - 128);
                               a1 = a0 + (size_t)64 * 64; }
            else             { a0 = p.A2 + (size_t)(m0 + arow) * 256 + (kh - 192);
                               a1 = a0 + (size_t)64 * 256; }
            cp16(ad, a0);
            cp16(ad + 64 * 80, a1);
        } else {
            const uint16_t* a0 = pA + it * 32;
            cp16(ad, a0);
            cp16(ad + 64 * 80, a0 + (size_t)64 * AK);
        }
        if constexpr (BN == 128) {
            cp16(bd, pB + it * 32);
            cp16(bd + 64 * 80, pB + (size_t)64 * BKH + it * 32);
        } else {
            if (tid < 128) cp16(bd, pB + it * 32);
        }
    };

    float acc[MT][NT][4];
    #pragma unroll
    for (int i = 0; i < MT; i++)
        #pragma unroll
        for (int j = 0; j < NT; j++)
            #pragma unroll
            for (int t = 0; t < 4; t++) acc[i][j][t] = 0.f;

    const int a_r = lane & 15, a_h = lane >> 4;
    const int b_g = lane >> 3, b_rl = lane & 7;
    const int b_row = (b_g >> 1) * 8 + b_rl;
    const int b_k16 = (b_g & 1) * 16;

    issue(0, 0); cp_commit();
    issue(1, 1); cp_commit();

    int s = 0, s2 = 2;
    for (int it = 0; it < ITERS; ++it) {
        cp_wait<1>();
        __syncthreads();
        if (it + 2 < ITERS) issue(it + 2, s2);
        cp_commit();

        const uint32_t Ab = As_sh + (uint32_t)s * ASTAGE_B;
        const uint32_t Bb = Bs_sh + (uint32_t)s * BSTAGE_B;
        #pragma unroll
        for (int ph = 0; ph < 2; ++ph) {
            uint32_t af[MT][4], bf[NT][2];
            #pragma unroll
            for (int mi = 0; mi < MT; ++mi)
                ldsm4(af[mi], Ab + (uint32_t)((wr * WTM + mi * 16 + a_r) * 80
                                              + ph * 32 + a_h * 16));
            #pragma unroll
            for (int pi = 0; pi < NT / 2; ++pi)
                ldsm4(&bf[2 * pi][0], Bb + (uint32_t)((wc * 32 + pi * 16 + b_row) * 80
                                                      + ph * 32 + b_k16));
            #pragma unroll
            for (int mi = 0; mi < MT; ++mi)
                #pragma unroll
                for (int ni = 0; ni < NT; ++ni)
                    mma16(acc[mi][ni], af[mi], bf[ni]);
        }
        if (++s == S) s = 0;
        if (++s2 == S) s2 = 0;
    }
    cp_wait<0>();
    __syncthreads();

    // ---------------- epilogues ----------------
    if constexpr (MODE == 0) {
        #pragma unroll
        for (int mi = 0; mi < MT; ++mi)
            #pragma unroll
            for (int ni = 0; ni < NT; ++ni) {
                int n = bx * 128 + wc * 32 + ni * 8 + q * 2;
                int m = m0 + wr * WTM + mi * 16 + rr;
                float b0v = p.bias0[n], b1v = p.bias0[n + 1];
                __half2 h0 = __floats2half2_rn(fmaxf(acc[mi][ni][0] + b0v, 0.f),
                                               fmaxf(acc[mi][ni][1] + b1v, 0.f));
                __half2 h1 = __floats2half2_rn(fmaxf(acc[mi][ni][2] + b0v, 0.f),
                                               fmaxf(acc[mi][ni][3] + b1v, 0.f));
                *(__half2*)(p.outH + (size_t)m * 256 + n) = h0;
                *(__half2*)(p.outH + (size_t)(m + 8) * 256 + n) = h1;
            }
    } else if constexpr (MODE == 3) {
        #pragma unroll
        for (int mi = 0; mi < MT; ++mi)
            #pragma unroll
            for (int ni = 0; ni < NT; ++ni) {
                int n = ni * 8 + q * 2;
                int m = m0 + wr * WTM + mi * 16 + rr;
                float b0v = p.bias0[n], b1v = p.bias0[n + 1];
                *(float2*)(p.out0 + (size_t)m * 32 + n) =
                    make_float2(acc[mi][ni][0] + b0v, acc[mi][ni][1] + b1v);
                *(float2*)(p.out0 + (size_t)(m + 8) * 32 + n) =
                    make_float2(acc[mi][ni][2] + b0v, acc[mi][ni][3] + b1v);
            }
    } else {
        // MODE 2: fused LSTM epilogue. Columns n = h_local*4 + gate (i,f,g,o)
        float* smc = (float*)smem_u;            // cell tile [128][33]
        float* smr = smc + 128 * 33;            // h tile   [128][33]
        const int h0 = bx * 32;
        for (int i = tid; i < 4096; i += 256) {
            int m = i >> 5, h = i & 31;
            smc[m * 33 + h] = p.cell[(size_t)(m0 + m) * 256 + h0 + h];
        }
        __syncthreads();

        const bool even = (q & 1) == 0;
        #pragma unroll
        for (int ni = 0; ni < NT; ++ni) {
            int nb = wc * 32 + ni * 8;
            int h_loc = (nb >> 2) + (q >> 1);
            int hg = h0 + h_loc;
            int g0 = (q & 1) * 2;
            float bb0 = p.bias0[g0 * 256 + hg] + p.bias1[g0 * 256 + hg];
            float bb1 = p.bias0[(g0 + 1) * 256 + hg] + p.bias1[(g0 + 1) * 256 + hg];
            #pragma unroll
            for (int mi = 0; mi < MT; ++mi) {
                float c0 = acc[mi][ni][0] + bb0, c1 = acc[mi][ni][1] + bb1;
                float c2 = acc[mi][ni][2] + bb0, c3 = acc[mi][ni][3] + bb1;
                float p0 = __shfl_xor_sync(~0u, c0, 1);
                float p1 = __shfl_xor_sync(~0u, c1, 1);
                float p2 = __shfl_xor_sync(~0u, c2, 1);
                float p3 = __shfl_xor_sync(~0u, c3, 1);
                if (even) {
                    int ml = wr * 64 + mi * 16 + rr;
                    float cp0 = smc[ml * 33 + h_loc];
                    float cp1 = smc[(ml + 8) * 33 + h_loc];
                    float cn0 = sigf(c1) * cp0 + sigf(c0) * tanhf(p0);
                    float hn0 = sigf(p1) * tanhf(cn0);
                    float cn1 = sigf(c3) * cp1 + sigf(c2) * tanhf(p2);
                    float hn1 = sigf(p3) * tanhf(cn1);
                    acc[mi][ni][0] = hn0; acc[mi][ni][1] = cn0;
                    acc[mi][ni][2] = hn1; acc[mi][ni][3] = cn1;
                }
            }
        }
        __syncthreads();
        #pragma unroll
        for (int ni = 0; ni < NT; ++ni) {
            int nb = wc * 32 + ni * 8;
            int h_loc = (nb >> 2) + (q >> 1);
            #pragma unroll
            for (int mi = 0; mi < MT; ++mi) {
                if (even) {
                    int ml = wr * 64 + mi * 16 + rr;
                    smr[ml * 33 + h_loc]       = acc[mi][ni][0];
                    smc[ml * 33 + h_loc]       = acc[mi][ni][1];
                    smr[(ml + 8) * 33 + h_loc] = acc[mi][ni][2];
                    smc[(ml + 8) * 33 + h_loc] = acc[mi][ni][3];
                }
            }
        }
        __syncthreads();
        for (int i = tid; i < 4096; i += 256) {
            int m = i >> 5, h = i & 31;
            size_t off = (size_t)(m0 + m) * 256 + h0 + h;
            float hv = smr[m * 33 + h];
            p.out0[off] = hv;
            p.out1[off] = smc[m * 33 + h];
            p.outH[off] = f2h(hv);
        }
    }
}

// ---------------- pack/convert prologue (vectorized activations) -------------
__global__ void pack_kernel(const float* __restrict__ mo, const float* __restrict__ hid,
                            const float* __restrict__ Wenc,
                            const float* __restrict__ Wq, const float* __restrict__ Wk,
                            const float* __restrict__ Wv,
                            const float* __restrict__ Wih, const float* __restrict__ Whh,
                            const float* __restrict__ Wdec,
                            uint16_t* __restrict__ moH, uint16_t* __restrict__ hidH,
                            uint16_t* __restrict__ wencH, uint16_t* __restrict__ wqkvH,
                            uint16_t* __restrict__ wcatH, uint16_t* __restrict__ wdecH)
{
    const int stride = gridDim.x * blockDim.x;
    const int g = blockIdx.x * blockDim.x + threadIdx.x;
    auto cvt4 = [](float4 v) -> uint2 {
        __half2 h01 = __floats2half2_rn(v.x, v.y);
        __half2 h23 = __floats2half2_rn(v.z, v.w);
        return make_uint2(*(uint32_t*)&h01, *(uint32_t*)&h23);
    };
    {
        const float4* s4 = (const float4*)mo;
        uint2* d4 = (uint2*)moH;
        for (size_t i = g; i < (size_t)NB * 128 / 4; i += stride) d4[i] = cvt4(s4[i]);
    }
    {
        const float4* s4 = (const float4*)hid;
        uint2* d4 = (uint2*)hidH;
        for (size_t i = g; i < (size_t)NB * 256 / 4; i += stride) d4[i] = cvt4(s4[i]);
    }
    for (int i = g; i < 256 * 128; i += stride) wencH[i] = f2h(Wenc[i]);
    for (int i = g; i < 64 * 256; i += stride) {
        wqkvH[i]         = f2h(Wq[i]);
        wqkvH[16384 + i] = f2h(Wk[i]);
        wqkvH[32768 + i] = f2h(Wv[i]);
    }
    for (int i = g; i < 1024 * 448; i += stride) {
        int n = i / 448, k = i - n * 448;
        int h = n >> 2, gg = n & 3, r = gg * 256 + h;
        float v = (k < 192) ? Wih[(size_t)r * 192 + k] : Whh[(size_t)r * 256 + (k - 192)];
        wcatH[i] = f2h(v);
    }
    for (int i = g; i < 32 * 256; i += stride) wdecH[i] = f2h(Wdec[i]);
}

// ---------------- launch ----------------------------------------------------
extern "C" void kernel_launch(void* const* d_in, const int* in_sizes, int n_in,
                              void* d_out, int out_size)
{
    const float* mo    = (const float*)d_in[0];
    const float* hid   = (const float*)d_in[1];
    const float* cell  = (const float*)d_in[2];
    const float* Wenc  = (const float*)d_in[3];
    const float* benc  = (const float*)d_in[4];
    const float* Wq    = (const float*)d_in[5];
    const float* Wk    = (const float*)d_in[6];
    const float* Wv    = (const float*)d_in[7];
    const float* bv    = (const float*)d_in[8];
    const float* Wih   = (const float*)d_in[9];
    const float* Whh   = (const float*)d_in[10];
    const float* bih   = (const float*)d_in[11];
    const float* bhh   = (const float*)d_in[12];
    const float* Wdec  = (const float*)d_in[13];
    const float* bdec  = (const float*)d_in[14];

    float* out   = (float*)d_out;
    float* m_act = out;
    float* h_out = out + (size_t)NB * NA_DIM;
    float* c_out = h_out + (size_t)NB * H_DIM;

    uint16_t *moH, *hidH, *xH, *eH, *hH, *wencH, *wqkvH, *wcatH, *wdecH;
    cudaGetSymbolAddress((void**)&moH,   g_moH);
    cudaGetSymbolAddress((void**)&hidH,  g_hidH);
    cudaGetSymbolAddress((void**)&xH,    g_xH);
    cudaGetSymbolAddress((void**)&eH,    g_eH);
    cudaGetSymbolAddress((void**)&hH,    g_hH);
    cudaGetSymbolAddress((void**)&wencH, g_wencH);
    cudaGetSymbolAddress((void**)&wqkvH, g_wqkvH);
    cudaGetSymbolAddress((void**)&wcatH, g_wcatH);
    cudaGetSymbolAddress((void**)&wdecH, g_wdecH);

    cudaFuncSetAttribute(gemm_f16<0>, cudaFuncAttributeMaxDynamicSharedMemorySize, 61440);
    cudaFuncSetAttribute(gemm_f16<2>, cudaFuncAttributeMaxDynamicSharedMemorySize, 61440);
    cudaFuncSetAttribute(gemm_f16<3>, cudaFuncAttributeMaxDynamicSharedMemorySize, 38400);
    cudaFuncSetAttribute(qkv_attn_kernel, cudaFuncAttributeMaxDynamicSharedMemorySize, QK_SMEM);

    // 0) pack + convert to fp16
    pack_kernel<<<2048, 256>>>(mo, hid, Wenc, Wq, Wk, Wv, Wih, Whh, Wdec,
                               moH, hidH, wencH, wqkvH, wcatH, wdecH);
    // 1) encoder
    {
        GP p{}; p.A = moH; p.B0 = wencH; p.bias0 = benc; p.outH = xH;
        gemm_f16<0><<<dim3(2, 1024), 256, 61440>>>(p);
    }
    // 2) fused qkv + attention -> eH
    qkv_attn_kernel<<<1024, 256, QK_SMEM>>>(xH, wqkvH, bv, eH);
    // 3) gates GEMM + fused LSTM
    {
        GP p{}; p.A = moH; p.A1 = eH; p.A2 = hidH;
        p.B0 = wcatH; p.bias0 = bih; p.bias1 = bhh;
        p.cell = cell; p.out0 = h_out; p.out1 = c_out; p.outH = hH;
        gemm_f16<2><<<dim3(8, 1024), 256, 61440>>>(p);
    }
    // 4) decoder
    {
        GP p{}; p.A = hH; p.B0 = wdecH; p.bias0 = bdec; p.out0 = m_act;
        gemm_f16<3><<<dim3(1, 1024), 256, 38400>>>(p);
    }
}